// round 9
// baseline (speedup 1.0000x reference)
#include <cuda_runtime.h>
#include <cuda_bf16.h>
#include <mma.h>
#include <cstdint>

using namespace nvcuda;

#define NN 100000
#define EE 1600000
#define NPART 98   // ceil(NN/1024)

// ---------------------------------------------------------------------------
// Static device scratch
// ---------------------------------------------------------------------------
__device__ __align__(256) float g_dinv[NN];
__device__ __align__(256) float g_xx [NN * 36];
__device__ __align__(256) float g_p0 [NN * 36];
__device__ __align__(256) float g_a1 [NN * 336];
__device__ __align__(256) float g_tt2[NN * 168];
__device__ __align__(256) float g_p2 [NN * 168];
__device__ __align__(256) float g_tt3[NN * 84];
__device__ __align__(256) float g_p3 [NN * 84];
__device__ __align__(256) float g_tt4[NN * 42];
__device__ __align__(256) float g_a4s[NN * 42];
__device__ __align__(256) float g_p5 [NN * 42];

// bf16 hi/lo weight planes, zero-padded to [Kp][Np]
__device__ __align__(256) __nv_bfloat16 g_w1hi[64 * 384];
__device__ __align__(256) __nv_bfloat16 g_w1lo[64 * 384];
__device__ __align__(256) __nv_bfloat16 g_w2hi[352 * 192];
__device__ __align__(256) __nv_bfloat16 g_w2lo[352 * 192];
__device__ __align__(256) __nv_bfloat16 g_w3hi[192 * 96];
__device__ __align__(256) __nv_bfloat16 g_w3lo[192 * 96];

__device__ __align__(256) int g_cnt[NN];
__device__ __align__(256) int g_cur[NN];
__device__ __align__(256) int g_off[NN + 1];
__device__ __align__(256) int g_adj[EE];
__device__ __align__(256) int g_part[NPART];

// ---------------------------------------------------------------------------
// Packed f32x2 helpers (FFMA2) — used by conv4 GEMM
// ---------------------------------------------------------------------------
__device__ __forceinline__ uint64_t pack2(float lo, float hi) {
    uint64_t r;
    asm("mov.b64 %0, {%1, %2};" : "=l"(r) : "f"(lo), "f"(hi));
    return r;
}
__device__ __forceinline__ void unpack2(uint64_t v, float& lo, float& hi) {
    asm("mov.b64 {%0, %1}, %2;" : "=f"(lo), "=f"(hi) : "l"(v));
}
__device__ __forceinline__ void ffma2(uint64_t& d, uint64_t a, uint64_t b) {
    asm("fma.rn.f32x2 %0, %1, %2, %3;" : "=l"(d) : "l"(a), "l"(b), "l"(d));
}

// ---------------------------------------------------------------------------
// CSR build
// ---------------------------------------------------------------------------
__global__ void k_zero2(int* cnt, int* cur) {
    int i = blockIdx.x * blockDim.x + threadIdx.x;
    if (i < NN) { cnt[i] = 0; cur[i] = 0; }
}
__global__ void k_count(const int* __restrict__ dst, int* cnt) {
    int e = blockIdx.x * blockDim.x + threadIdx.x;
    if (e < EE) atomicAdd(&cnt[dst[e]], 1);
}
__global__ void k_scan1(const int* __restrict__ cnt, int* __restrict__ off,
                        int* __restrict__ part, float* __restrict__ dinv) {
    __shared__ int s[1024];
    int t = threadIdx.x;
    int i = blockIdx.x * 1024 + t;
    int v = (i < NN) ? cnt[i] : 0;
    if (i < NN) dinv[i] = rsqrtf((float)v + 1.0f);
    s[t] = v;
    __syncthreads();
    for (int d = 1; d < 1024; d <<= 1) {
        int u = (t >= d) ? s[t - d] : 0;
        __syncthreads();
        s[t] += u;
        __syncthreads();
    }
    if (i < NN) off[i] = s[t] - v;
    if (t == 1023) part[blockIdx.x] = s[1023];
}
__global__ void k_scan2(int* part, int* off) {
    if (threadIdx.x == 0 && blockIdx.x == 0) {
        int run = 0;
        for (int p = 0; p < NPART; p++) { int c = part[p]; part[p] = run; run += c; }
        off[NN] = EE;
    }
}
__global__ void k_scan3(int* __restrict__ off, const int* __restrict__ part) {
    int i = blockIdx.x * 1024 + threadIdx.x;
    if (i < NN) off[i] += part[blockIdx.x];
}
__global__ void k_fill(const int* __restrict__ src, const int* __restrict__ dst,
                       const int* __restrict__ off, int* cur, int* __restrict__ adj) {
    int e = blockIdx.x * blockDim.x + threadIdx.x;
    if (e >= EE) return;
    int d = dst[e];
    int p = off[d] + atomicAdd(&cur[d], 1);
    adj[p] = src[e];
}

// ---------------------------------------------------------------------------
// Elementwise: xx = dinv[n] * pad(x)
// ---------------------------------------------------------------------------
__global__ void k_pad_scale(const float* __restrict__ x, const float* __restrict__ dinv,
                            float* __restrict__ xx) {
    int i = blockIdx.x * blockDim.x + threadIdx.x;
    if (i >= NN * 36) return;
    int n = i / 36, c = i - n * 36;
    float v = (c < 35) ? x[(size_t)n * 35 + c] : 0.0f;
    xx[i] = v * dinv[n];
}

// W [K][Nd] -> hi/lo bf16 planes [Kp][Np], zero-padded
__global__ void k_wsplit(const float* __restrict__ W,
                         __nv_bfloat16* __restrict__ hi, __nv_bfloat16* __restrict__ lo,
                         int K, int Nd, int Kp, int Np) {
    int i = blockIdx.x * blockDim.x + threadIdx.x;
    if (i >= Kp * Np) return;
    int k = i / Np, n = i - k * Np;
    float v = (k < K && n < Nd) ? W[(size_t)k * Nd + n] : 0.0f;
    __nv_bfloat16 h = __float2bfloat16_rn(v);
    hi[i] = h;
    lo[i] = __float2bfloat16_rn(v - __bfloat162float(h));
}

// ---------------------------------------------------------------------------
// CSR gather aggregation (2-way unrolled)
// ---------------------------------------------------------------------------
template <int D, int VEC, bool RBS>
__global__ void __launch_bounds__(252)
k_agg(const int* __restrict__ off, const int* __restrict__ adj,
      const float* __restrict__ dinv, const float* __restrict__ tt,
      const float* __restrict__ bias, float* __restrict__ p) {
    constexpr int G = D / VEC;
    constexpr int NPB = 252 / G;
    int g = threadIdx.x / G;
    int c = (threadIdx.x - g * G) * VEC;
    int node = blockIdx.x * NPB + g;
    if (node >= NN) return;
    int ib = off[node], ie = off[node + 1];
    float sc = dinv[node];
    if (VEC == 4) {
        float4 acc = *(const float4*)(tt + (size_t)node * D + c);
        float4 acc2 = make_float4(0.f, 0.f, 0.f, 0.f);
        int i = ib;
        for (; i + 2 <= ie; i += 2) {
            int s0 = adj[i], s1 = adj[i + 1];
            float4 v0 = *(const float4*)(tt + (size_t)s0 * D + c);
            float4 v1 = *(const float4*)(tt + (size_t)s1 * D + c);
            acc.x += v0.x; acc.y += v0.y; acc.z += v0.z; acc.w += v0.w;
            acc2.x += v1.x; acc2.y += v1.y; acc2.z += v1.z; acc2.w += v1.w;
        }
        if (i < ie) {
            int s0 = adj[i];
            float4 v0 = *(const float4*)(tt + (size_t)s0 * D + c);
            acc.x += v0.x; acc.y += v0.y; acc.z += v0.z; acc.w += v0.w;
        }
        acc.x = (acc.x + acc2.x) * sc; acc.y = (acc.y + acc2.y) * sc;
        acc.z = (acc.z + acc2.z) * sc; acc.w = (acc.w + acc2.w) * sc;
        if (RBS) {
            acc.x = fmaxf(acc.x + bias[c + 0], 0.f) * sc;
            acc.y = fmaxf(acc.y + bias[c + 1], 0.f) * sc;
            acc.z = fmaxf(acc.z + bias[c + 2], 0.f) * sc;
            acc.w = fmaxf(acc.w + bias[c + 3], 0.f) * sc;
        }
        *(float4*)(p + (size_t)node * D + c) = acc;
    } else {
        float2 acc = *(const float2*)(tt + (size_t)node * D + c);
        float2 acc2 = make_float2(0.f, 0.f);
        int i = ib;
        for (; i + 2 <= ie; i += 2) {
            int s0 = adj[i], s1 = adj[i + 1];
            float2 v0 = *(const float2*)(tt + (size_t)s0 * D + c);
            float2 v1 = *(const float2*)(tt + (size_t)s1 * D + c);
            acc.x += v0.x; acc.y += v0.y;
            acc2.x += v1.x; acc2.y += v1.y;
        }
        if (i < ie) {
            int s0 = adj[i];
            float2 v0 = *(const float2*)(tt + (size_t)s0 * D + c);
            acc.x += v0.x; acc.y += v0.y;
        }
        acc.x = (acc.x + acc2.x) * sc;
        acc.y = (acc.y + acc2.y) * sc;
        if (RBS) {
            acc.x = fmaxf(acc.x + bias[c + 0], 0.f) * sc;
            acc.y = fmaxf(acc.y + bias[c + 1], 0.f) * sc;
        }
        *(float2*)(p + (size_t)node * D + c) = acc;
    }
}

// ---------------------------------------------------------------------------
// wmma bf16x3 GEMM: C = f(A) @ W  with W pre-split into bf16 hi/lo planes.
// Block tile 128x96, 8 warps (4x2), warp tile 32x48 (2x3 of 16x16 frags).
// A is split to hi/lo bf16 at load; acc = Ah*Bh + Ah*Bl + Al*Bh in fp32.
// IN_RELU:  a = relu(A + binA) at load.  OUT_RELU: c = relu(c + bout).
// OUT_SCALE: c *= dinv[row].
// ---------------------------------------------------------------------------
template <bool IN_RELU, bool OUT_RELU, bool OUT_SCALE>
__global__ void __launch_bounds__(256)
k_wgemm(const float* __restrict__ A, int lda, const float* __restrict__ binA,
        const __nv_bfloat16* __restrict__ Bhi, const __nv_bfloat16* __restrict__ Blo,
        const float* __restrict__ bout, float* __restrict__ C,
        const float* __restrict__ dinv, int M, int K, int Nd, int Kp, int Np) {
    __shared__ __nv_bfloat16 Ash[128][32];
    __shared__ __nv_bfloat16 Asl[128][32];
    __shared__ __nv_bfloat16 Bsh[32][96];
    __shared__ __nv_bfloat16 Bsl[32][96];
    __shared__ float stage[8][256];

    int tid = threadIdx.x;
    int wid = tid >> 5;
    int lane = tid & 31;
    int wm = wid & 3;          // 0..3 -> 32-row slab
    int wn = wid >> 2;         // 0..1 -> 48-col slab
    int row0 = blockIdx.x * 128;
    int col0 = blockIdx.y * 96;

    wmma::fragment<wmma::accumulator, 16, 16, 16, float> acc[2][3];
#pragma unroll
    for (int mi = 0; mi < 2; mi++)
#pragma unroll
        for (int ni = 0; ni < 3; ni++) wmma::fill_fragment(acc[mi][ni], 0.0f);

    int nch = Kp >> 5;
    for (int ch = 0; ch < nch; ch++) {
        // A chunk [128 x 32] fp32 -> bf16 hi/lo
#pragma unroll
        for (int l = 0; l < 16; l++) {
            int i = tid + l * 256;
            int r = i >> 5, j = i & 31;
            int grow = row0 + r, gk = ch * 32 + j;
            float a = 0.0f;
            if (grow < M && gk < K) {
                a = A[(size_t)grow * lda + gk];
                if (IN_RELU) a = fmaxf(a + binA[gk], 0.0f);
            }
            __nv_bfloat16 h = __float2bfloat16_rn(a);
            Ash[r][j] = h;
            Asl[r][j] = __float2bfloat16_rn(a - __bfloat162float(h));
        }
        // B chunk [32 x 96] from padded planes (4-bf16 vectors)
#pragma unroll
        for (int l = 0; l < 3; l++) {
            int idx = tid + l * 256;
            int k = idx / 24, j4 = (idx - k * 24) * 4;
            size_t src = (size_t)(ch * 32 + k) * Np + col0 + j4;
            *(uint2*)&Bsh[k][j4] = *(const uint2*)(Bhi + src);
            *(uint2*)&Bsl[k][j4] = *(const uint2*)(Blo + src);
        }
        __syncthreads();

#pragma unroll
        for (int kk = 0; kk < 32; kk += 16) {
            wmma::fragment<wmma::matrix_a, 16, 16, 16, __nv_bfloat16, wmma::row_major> ah[2], al[2];
            wmma::fragment<wmma::matrix_b, 16, 16, 16, __nv_bfloat16, wmma::row_major> bh[3], bl[3];
#pragma unroll
            for (int mi = 0; mi < 2; mi++) {
                const __nv_bfloat16* ap = &Ash[wm * 32 + mi * 16][kk];
                const __nv_bfloat16* alp = &Asl[wm * 32 + mi * 16][kk];
                wmma::load_matrix_sync(ah[mi], ap, 32);
                wmma::load_matrix_sync(al[mi], alp, 32);
            }
#pragma unroll
            for (int ni = 0; ni < 3; ni++) {
                const __nv_bfloat16* bp = &Bsh[kk][wn * 48 + ni * 16];
                const __nv_bfloat16* blp = &Bsl[kk][wn * 48 + ni * 16];
                wmma::load_matrix_sync(bh[ni], bp, 96);
                wmma::load_matrix_sync(bl[ni], blp, 96);
            }
#pragma unroll
            for (int mi = 0; mi < 2; mi++)
#pragma unroll
                for (int ni = 0; ni < 3; ni++) {
                    wmma::mma_sync(acc[mi][ni], ah[mi], bh[ni], acc[mi][ni]);
                    wmma::mma_sync(acc[mi][ni], ah[mi], bl[ni], acc[mi][ni]);
                    wmma::mma_sync(acc[mi][ni], al[mi], bh[ni], acc[mi][ni]);
                }
        }
        __syncthreads();
    }

    // epilogue: stage each 16x16 tile, scale/bias, store
#pragma unroll
    for (int mi = 0; mi < 2; mi++) {
#pragma unroll
        for (int ni = 0; ni < 3; ni++) {
            wmma::store_matrix_sync(stage[wid], acc[mi][ni], 16, wmma::mem_row_major);
            __syncwarp();
            int r = lane >> 1, cg = (lane & 1) * 8;
            int grow = row0 + wm * 32 + mi * 16 + r;
            int col = col0 + wn * 48 + ni * 16 + cg;
            if (grow < M) {
                float s = OUT_SCALE ? dinv[grow] : 1.0f;
                const float* st = &stage[wid][r * 16 + cg];
                if (col < Nd) {
                    float4 v = *(const float4*)st;
                    if (OUT_RELU) {
                        v.x = fmaxf(v.x + bout[col + 0], 0.f);
                        v.y = fmaxf(v.y + bout[col + 1], 0.f);
                        v.z = fmaxf(v.z + bout[col + 2], 0.f);
                        v.w = fmaxf(v.w + bout[col + 3], 0.f);
                    }
                    if (OUT_SCALE) { v.x *= s; v.y *= s; v.z *= s; v.w *= s; }
                    *(float4*)(C + (size_t)grow * Nd + col) = v;
                }
                if (col + 4 < Nd) {
                    float4 v = *(const float4*)(st + 4);
                    if (OUT_RELU) {
                        v.x = fmaxf(v.x + bout[col + 4], 0.f);
                        v.y = fmaxf(v.y + bout[col + 5], 0.f);
                        v.z = fmaxf(v.z + bout[col + 6], 0.f);
                        v.w = fmaxf(v.w + bout[col + 7], 0.f);
                    }
                    if (OUT_SCALE) { v.x *= s; v.y *= s; v.z *= s; v.w *= s; }
                    *(float4*)(C + (size_t)grow * Nd + col + 4) = v;
                }
            }
            __syncwarp();
        }
    }
}

// ---------------------------------------------------------------------------
// FFMA2 GEMM 128x64, double-buffered (conv4 only)
// ---------------------------------------------------------------------------
template <bool IN_RELU, bool OUT_RELU, bool OUT_SCALE>
__global__ void __launch_bounds__(256)
k_gemm2(const float* __restrict__ A, int lda, const float* __restrict__ binA,
        const float* __restrict__ B, const float* __restrict__ bout,
        float* __restrict__ C, const float* __restrict__ dinv,
        int M, int K, int Nd) {
    __shared__ uint64_t As[2][16][130];
    __shared__ uint64_t Bs[2][16][34];

    int tid = threadIdx.x;
    int tx = tid & 15;
    int ty = tid >> 4;
    int row0 = blockIdx.x * 128;
    int col0 = blockIdx.y * 64;

    uint64_t acc[8][2];
#pragma unroll
    for (int i = 0; i < 8; i++) { acc[i][0] = 0ull; acc[i][1] = 0ull; }

    auto load_tile = [&](int k0, int buf) {
#pragma unroll
        for (int l = 0; l < 8; l++) {
            int idx = tid + l * 256;
            int kk = idx & 15, rr = idx >> 4;
            int grow = row0 + rr, gk = k0 + kk;
            float a = 0.0f;
            if (grow < M && gk < K) {
                a = A[(size_t)grow * lda + gk];
                if (IN_RELU) a = fmaxf(a + binA[gk], 0.0f);
            }
            As[buf][kk][rr] = pack2(a, a);
        }
#pragma unroll
        for (int l = 0; l < 2; l++) {
            int idx = tid + l * 256;
            int cp = idx & 31, kk = idx >> 5;
            int gk = k0 + kk, gc = col0 + 2 * cp;
            float2 bv = make_float2(0.0f, 0.0f);
            if (gk < K && gc < Nd) bv = *(const float2*)(B + (size_t)gk * Nd + gc);
            Bs[buf][kk][cp] = pack2(bv.x, bv.y);
        }
    };

    int nt = (K + 15) >> 4;
    load_tile(0, 0);
    __syncthreads();

    for (int t = 0; t < nt; t++) {
        int buf = t & 1;
        if (t + 1 < nt) load_tile((t + 1) * 16, buf ^ 1);
#pragma unroll
        for (int kk = 0; kk < 16; kk++) {
            ulonglong2 bb = *(const ulonglong2*)&Bs[buf][kk][2 * tx];
#pragma unroll
            for (int i = 0; i < 4; i++) {
                ulonglong2 aa = *(const ulonglong2*)&As[buf][kk][ty * 8 + 2 * i];
                ffma2(acc[2 * i][0],     aa.x, bb.x);
                ffma2(acc[2 * i][1],     aa.x, bb.y);
                ffma2(acc[2 * i + 1][0], aa.y, bb.x);
                ffma2(acc[2 * i + 1][1], aa.y, bb.y);
            }
        }
        __syncthreads();
    }

    int colb = col0 + tx * 4;
#pragma unroll
    for (int i = 0; i < 8; i++) {
        int row = row0 + ty * 8 + i;
        if (row >= M) continue;
        float vv[4];
        unpack2(acc[i][0], vv[0], vv[1]);
        unpack2(acc[i][1], vv[2], vv[3]);
        float s = OUT_SCALE ? dinv[row] : 1.0f;
#pragma unroll
        for (int j = 0; j < 4; j++) {
            int col = colb + j;
            if (col >= Nd) continue;
            float v = vv[j];
            if (OUT_RELU) v = fmaxf(v + bout[col], 0.0f);
            if (OUT_SCALE) v *= s;
            C[(size_t)row * Nd + col] = v;
        }
    }
}

// ---------------------------------------------------------------------------
// Final fused head
// ---------------------------------------------------------------------------
__global__ void __launch_bounds__(128)
k_final(const float* __restrict__ p5,
        const float* __restrict__ Wmu, const float* __restrict__ bmu,
        const float* __restrict__ Wls, const float* __restrict__ bls,
        const float* __restrict__ eps, float* __restrict__ out) {
    __shared__ float sWmu[42 * 21];
    __shared__ float sWls[42 * 21];
    __shared__ float sbmu[21];
    __shared__ float sbls[21];
    for (int i = threadIdx.x; i < 42 * 21; i += blockDim.x) {
        sWmu[i] = Wmu[i];
        sWls[i] = Wls[i];
    }
    if (threadIdx.x < 21) {
        sbmu[threadIdx.x] = bmu[threadIdx.x];
        sbls[threadIdx.x] = bls[threadIdx.x];
    }
    __syncthreads();

    int n = blockIdx.x * blockDim.x + threadIdx.x;
    if (n >= NN) return;

    float xr[42];
#pragma unroll
    for (int i = 0; i < 42; i++) xr[i] = p5[(size_t)n * 42 + i];

    float z[21];
#pragma unroll
    for (int j = 0; j < 21; j++) {
        float mu = sbmu[j];
        float ls = sbls[j];
#pragma unroll
        for (int i = 0; i < 42; i++) {
            mu += xr[i] * sWmu[i * 21 + j];
            ls += xr[i] * sWls[i * 21 + j];
        }
        ls = fminf(ls, 10.0f);
        z[j] = mu + eps[(size_t)n * 21 + j] * expf(ls);
    }
    float m = z[0];
#pragma unroll
    for (int j = 1; j < 21; j++) m = fmaxf(m, z[j]);
    float s = 0.0f;
#pragma unroll
    for (int j = 0; j < 21; j++) s += expf(z[j] - m);
    float lse = m + logf(s);
#pragma unroll
    for (int j = 0; j < 21; j++) out[(size_t)n * 21 + j] = z[j] - lse;
}

// ---------------------------------------------------------------------------
static inline int cdiv(long a, long b) { return (int)((a + b - 1) / b); }

extern "C" void kernel_launch(void* const* d_in, const int* in_sizes, int n_in,
                              void* d_out, int out_size) {
    const float* x    = (const float*)d_in[0];
    const int*   ei   = (const int*)  d_in[1];
    const float* eps  = (const float*)d_in[2];
    const float* W1   = (const float*)d_in[3];
    const float* b1   = (const float*)d_in[4];
    const float* W2   = (const float*)d_in[5];
    const float* b2   = (const float*)d_in[6];
    const float* W3   = (const float*)d_in[7];
    const float* b3   = (const float*)d_in[8];
    const float* W4   = (const float*)d_in[9];
    const float* b4   = (const float*)d_in[10];
    const float* Wmu  = (const float*)d_in[11];
    const float* bmu  = (const float*)d_in[12];
    const float* Wls  = (const float*)d_in[13];
    const float* bls  = (const float*)d_in[14];
    float* out = (float*)d_out;

    float *dinv, *xx, *p0, *a1, *tt2, *p2, *tt3, *p3, *tt4, *a4s, *p5;
    __nv_bfloat16 *w1hi, *w1lo, *w2hi, *w2lo, *w3hi, *w3lo;
    int *cnt, *cur, *off, *adj, *part;
    cudaGetSymbolAddress((void**)&dinv, g_dinv);
    cudaGetSymbolAddress((void**)&xx,  g_xx);
    cudaGetSymbolAddress((void**)&p0,  g_p0);
    cudaGetSymbolAddress((void**)&a1,  g_a1);
    cudaGetSymbolAddress((void**)&tt2, g_tt2);
    cudaGetSymbolAddress((void**)&p2,  g_p2);
    cudaGetSymbolAddress((void**)&tt3, g_tt3);
    cudaGetSymbolAddress((void**)&p3,  g_p3);
    cudaGetSymbolAddress((void**)&tt4, g_tt4);
    cudaGetSymbolAddress((void**)&a4s, g_a4s);
    cudaGetSymbolAddress((void**)&p5,  g_p5);
    cudaGetSymbolAddress((void**)&w1hi, g_w1hi);
    cudaGetSymbolAddress((void**)&w1lo, g_w1lo);
    cudaGetSymbolAddress((void**)&w2hi, g_w2hi);
    cudaGetSymbolAddress((void**)&w2lo, g_w2lo);
    cudaGetSymbolAddress((void**)&w3hi, g_w3hi);
    cudaGetSymbolAddress((void**)&w3lo, g_w3lo);
    cudaGetSymbolAddress((void**)&cnt, g_cnt);
    cudaGetSymbolAddress((void**)&cur, g_cur);
    cudaGetSymbolAddress((void**)&off, g_off);
    cudaGetSymbolAddress((void**)&adj, g_adj);
    cudaGetSymbolAddress((void**)&part, g_part);

    const int* src = ei;
    const int* dst = ei + EE;

    // ---- CSR build + normalization; weight hi/lo split prep ----
    k_zero2<<<cdiv(NN, 256), 256>>>(cnt, cur);
    k_count<<<cdiv(EE, 256), 256>>>(dst, cnt);
    k_wsplit<<<cdiv(64 * 384, 256), 256>>>(W1, w1hi, w1lo, 35, 336, 64, 384);
    k_wsplit<<<cdiv(352 * 192, 256), 256>>>(W2, w2hi, w2lo, 336, 168, 352, 192);
    k_wsplit<<<cdiv(192 * 96, 256), 256>>>(W3, w3hi, w3lo, 168, 84, 192, 96);
    k_scan1<<<NPART, 1024>>>(cnt, off, part, dinv);
    k_scan2<<<1, 32>>>(part, off);
    k_scan3<<<NPART, 1024>>>(off, part);
    k_fill<<<cdiv(EE, 256), 256>>>(src, dst, off, cur, adj);

    int gm = cdiv(NN, 128);

    // ---- conv1: aggregate x (D=36), then wmma GEMM 35->336 (+b1, relu) ----
    k_pad_scale<<<cdiv((long)NN * 36, 256), 256>>>(x, dinv, xx);
    k_agg<36, 4, false><<<cdiv(NN, 28), 252>>>(off, adj, dinv, xx, nullptr, p0);
    k_wgemm<false, true, false><<<dim3(gm, 4), 256>>>(
        p0, 36, nullptr, w1hi, w1lo, b1, a1, nullptr, NN, 35, 336, 64, 384);

    // ---- conv2: wmma GEMM 336->168 (scaled out), aggregate ----
    k_wgemm<false, false, true><<<dim3(gm, 2), 256>>>(
        a1, 336, nullptr, w2hi, w2lo, nullptr, tt2, dinv, NN, 336, 168, 352, 192);
    k_agg<168, 4, false><<<cdiv(NN, 6), 252>>>(off, adj, dinv, tt2, nullptr, p2);

    // ---- conv3: in = relu(p2+b2), wmma GEMM 168->84, scaled out ----
    k_wgemm<true, false, true><<<dim3(gm, 1), 256>>>(
        p2, 168, b2, w3hi, w3lo, nullptr, tt3, dinv, NN, 168, 84, 192, 96);
    k_agg<84, 4, false><<<cdiv(NN, 12), 252>>>(off, adj, dinv, tt3, nullptr, p3);

    // ---- conv4 (FFMA2): in = relu(p3+b3), 84->42; agg fuses relu+bias ----
    k_gemm2<true, false, true><<<dim3(gm, 1), 256>>>(
        p3, 84, b3, W4, nullptr, tt4, dinv, NN, 84, 42);
    k_agg<42, 2, true><<<cdiv(NN, 12), 252>>>(off, adj, dinv, tt4, b4, a4s);

    // ---- shared head propagation ----
    k_agg<42, 2, false><<<cdiv(NN, 12), 252>>>(off, adj, dinv, a4s, nullptr, p5);

    // ---- fused heads + reparam + log_softmax ----
    k_final<<<cdiv(NN, 128), 128>>>(p5, Wmu, bmu, Wls, bls, eps, out);
}

// round 10
// speedup vs baseline: 2.1267x; 2.1267x over previous
#include <cuda_runtime.h>
#include <cuda_fp16.h>
#include <mma.h>
#include <cstdint>

using namespace nvcuda;

#define NN 100000
#define EE 1600000
#define NPART 98   // ceil(NN/1024)

// ---------------------------------------------------------------------------
// Static device scratch — all activations fp16
// ---------------------------------------------------------------------------
__device__ __align__(256) float  g_dinv[NN];
__device__ __align__(256) __half g_xx [NN * 36];
__device__ __align__(256) __half g_p0 [NN * 36];
__device__ __align__(256) __half g_a1 [NN * 336];
__device__ __align__(256) __half g_tt2[NN * 168];
__device__ __align__(256) __half g_p2 [NN * 168];
__device__ __align__(256) __half g_tt3[NN * 84];
__device__ __align__(256) __half g_p3 [NN * 84];
__device__ __align__(256) __half g_tt4[NN * 42];
__device__ __align__(256) __half g_a4s[NN * 42];
__device__ __align__(256) __half g_p5 [NN * 42];

// fp16 hi/lo weight planes, zero-padded to [Kp][Np]
__device__ __align__(256) __half g_w1hi[64 * 384];
__device__ __align__(256) __half g_w1lo[64 * 384];
__device__ __align__(256) __half g_w2hi[352 * 192];
__device__ __align__(256) __half g_w2lo[352 * 192];
__device__ __align__(256) __half g_w3hi[192 * 96];
__device__ __align__(256) __half g_w3lo[192 * 96];

__device__ __align__(256) int g_cnt[NN];
__device__ __align__(256) int g_cur[NN];
__device__ __align__(256) int g_off[NN + 1];
__device__ __align__(256) int g_adj[EE];
__device__ __align__(256) int g_part[NPART];

// ---------------------------------------------------------------------------
// Packed f32x2 helpers (FFMA2) — conv4 GEMM
// ---------------------------------------------------------------------------
__device__ __forceinline__ uint64_t pack2(float lo, float hi) {
    uint64_t r;
    asm("mov.b64 %0, {%1, %2};" : "=l"(r) : "f"(lo), "f"(hi));
    return r;
}
__device__ __forceinline__ void unpack2(uint64_t v, float& lo, float& hi) {
    asm("mov.b64 {%0, %1}, %2;" : "=f"(lo), "=f"(hi) : "l"(v));
}
__device__ __forceinline__ void ffma2(uint64_t& d, uint64_t a, uint64_t b) {
    asm("fma.rn.f32x2 %0, %1, %2, %3;" : "=l"(d) : "l"(a), "l"(b), "l"(d));
}

// ---------------------------------------------------------------------------
// half vector load/store helpers
// ---------------------------------------------------------------------------
template <int V>
__device__ __forceinline__ void ldh(const __half* p, float* f) {
    if constexpr (V == 8) {
        uint4 u = *(const uint4*)p;
        const __half2* h = (const __half2*)&u;
#pragma unroll
        for (int k = 0; k < 4; k++) {
            float2 t = __half22float2(h[k]);
            f[2 * k] = t.x; f[2 * k + 1] = t.y;
        }
    } else if constexpr (V == 4) {
        uint2 u = *(const uint2*)p;
        const __half2* h = (const __half2*)&u;
#pragma unroll
        for (int k = 0; k < 2; k++) {
            float2 t = __half22float2(h[k]);
            f[2 * k] = t.x; f[2 * k + 1] = t.y;
        }
    } else {
        uint32_t u = *(const uint32_t*)p;
        float2 t = __half22float2(*(const __half2*)&u);
        f[0] = t.x; f[1] = t.y;
    }
}
template <int V>
__device__ __forceinline__ void sth(__half* p, const float* f) {
    if constexpr (V == 8) {
        uint4 u;
        __half2* h = (__half2*)&u;
#pragma unroll
        for (int k = 0; k < 4; k++)
            h[k] = __floats2half2_rn(f[2 * k], f[2 * k + 1]);
        *(uint4*)p = u;
    } else if constexpr (V == 4) {
        uint2 u;
        __half2* h = (__half2*)&u;
#pragma unroll
        for (int k = 0; k < 2; k++)
            h[k] = __floats2half2_rn(f[2 * k], f[2 * k + 1]);
        *(uint2*)p = u;
    } else {
        __half2 h = __floats2half2_rn(f[0], f[1]);
        *(uint32_t*)p = *(uint32_t*)&h;
    }
}

// ---------------------------------------------------------------------------
// CSR build
// ---------------------------------------------------------------------------
__global__ void k_zero2(int* cnt, int* cur) {
    int i = blockIdx.x * blockDim.x + threadIdx.x;
    if (i < NN) { cnt[i] = 0; cur[i] = 0; }
}
__global__ void k_count(const int* __restrict__ dst, int* cnt) {
    int e = blockIdx.x * blockDim.x + threadIdx.x;
    if (e < EE) atomicAdd(&cnt[dst[e]], 1);
}
__global__ void k_scan1(const int* __restrict__ cnt, int* __restrict__ off,
                        int* __restrict__ part, float* __restrict__ dinv) {
    __shared__ int s[1024];
    int t = threadIdx.x;
    int i = blockIdx.x * 1024 + t;
    int v = (i < NN) ? cnt[i] : 0;
    if (i < NN) dinv[i] = rsqrtf((float)v + 1.0f);
    s[t] = v;
    __syncthreads();
    for (int d = 1; d < 1024; d <<= 1) {
        int u = (t >= d) ? s[t - d] : 0;
        __syncthreads();
        s[t] += u;
        __syncthreads();
    }
    if (i < NN) off[i] = s[t] - v;
    if (t == 1023) part[blockIdx.x] = s[1023];
}
__global__ void k_scan2(int* part, int* off) {
    if (threadIdx.x == 0 && blockIdx.x == 0) {
        int run = 0;
        for (int p = 0; p < NPART; p++) { int c = part[p]; part[p] = run; run += c; }
        off[NN] = EE;
    }
}
__global__ void k_scan3(int* __restrict__ off, const int* __restrict__ part) {
    int i = blockIdx.x * 1024 + threadIdx.x;
    if (i < NN) off[i] += part[blockIdx.x];
}
__global__ void k_fill(const int* __restrict__ src, const int* __restrict__ dst,
                       const int* __restrict__ off, int* cur, int* __restrict__ adj) {
    int e = blockIdx.x * blockDim.x + threadIdx.x;
    if (e >= EE) return;
    int d = dst[e];
    int p = off[d] + atomicAdd(&cur[d], 1);
    adj[p] = src[e];
}

// ---------------------------------------------------------------------------
// xx = fp16(dinv[n] * pad(x))
// ---------------------------------------------------------------------------
__global__ void k_pad_scale(const float* __restrict__ x, const float* __restrict__ dinv,
                            __half* __restrict__ xx) {
    int i = blockIdx.x * blockDim.x + threadIdx.x;
    if (i >= NN * 36) return;
    int n = i / 36, c = i - n * 36;
    float v = (c < 35) ? x[(size_t)n * 35 + c] : 0.0f;
    xx[i] = __float2half_rn(v * dinv[n]);
}

// W [K][Nd] fp32 -> fp16 hi/lo planes [Kp][Np], zero-padded
__global__ void k_wsplit(const float* __restrict__ W,
                         __half* __restrict__ hi, __half* __restrict__ lo,
                         int K, int Nd, int Kp, int Np) {
    int i = blockIdx.x * blockDim.x + threadIdx.x;
    if (i >= Kp * Np) return;
    int k = i / Np, n = i - k * Np;
    float v = (k < K && n < Nd) ? W[(size_t)k * Nd + n] : 0.0f;
    __half h = __float2half_rn(v);
    hi[i] = h;
    lo[i] = __float2half_rn(v - __half2float(h));
}

// ---------------------------------------------------------------------------
// CSR gather aggregation on fp16 arrays (fp32 accumulate, 2-way unrolled):
//   base: p[d] = fp16(dinv[d] * (tt[d] + sum_{s in N(d)} tt[s]))
//   RBS:  p[d] = fp16(dinv[d] * relu(base + bias[c]))
// ---------------------------------------------------------------------------
template <int D, int V, bool RBS>
__global__ void __launch_bounds__(252)
k_agg(const int* __restrict__ off, const int* __restrict__ adj,
      const float* __restrict__ dinv, const __half* __restrict__ tt,
      const float* __restrict__ bias, __half* __restrict__ p) {
    constexpr int G = D / V;
    constexpr int NPB = 252 / G;
    int g = threadIdx.x / G;
    int c = (threadIdx.x - g * G) * V;
    int node = blockIdx.x * NPB + g;
    if (node >= NN) return;
    int ib = off[node], ie = off[node + 1];
    float acc[V], acc2[V], tmp[V];
    ldh<V>(tt + (size_t)node * D + c, acc);
#pragma unroll
    for (int v = 0; v < V; v++) acc2[v] = 0.0f;
    int i = ib;
    for (; i + 2 <= ie; i += 2) {
        int s0 = adj[i], s1 = adj[i + 1];
        ldh<V>(tt + (size_t)s0 * D + c, tmp);
#pragma unroll
        for (int v = 0; v < V; v++) acc[v] += tmp[v];
        ldh<V>(tt + (size_t)s1 * D + c, tmp);
#pragma unroll
        for (int v = 0; v < V; v++) acc2[v] += tmp[v];
    }
    if (i < ie) {
        int s0 = adj[i];
        ldh<V>(tt + (size_t)s0 * D + c, tmp);
#pragma unroll
        for (int v = 0; v < V; v++) acc[v] += tmp[v];
    }
    float sc = dinv[node];
#pragma unroll
    for (int v = 0; v < V; v++) {
        float f = (acc[v] + acc2[v]) * sc;
        if (RBS) f = fmaxf(f + bias[c + v], 0.0f) * sc;
        acc[v] = f;
    }
    sth<V>(p + (size_t)node * D + c, acc);
}

// ---------------------------------------------------------------------------
// wmma fp16 GEMM: C = f(A) @ W, A fp16 (exact), W fp16 hi/lo (2 products).
// Block 128x96, 8 warps (4x2), warp tile 32x48. fp32 accumulate.
// IN_RELU: a = relu(A + binA) at load. OUT_RELU: c = relu(c + bout).
// OUT_SCALE: c *= dinv[row]. A has Kphys physical cols (mult of 4).
// ---------------------------------------------------------------------------
template <bool IN_RELU, bool OUT_RELU, bool OUT_SCALE>
__global__ void __launch_bounds__(256)
k_wgemm(const __half* __restrict__ A, int Kphys, const float* __restrict__ binA,
        const __half* __restrict__ Bhi, const __half* __restrict__ Blo,
        const float* __restrict__ bout, __half* __restrict__ C,
        const float* __restrict__ dinv, int M, int Nd, int Kp, int Np) {
    __shared__ __half Ash[128][40];
    __shared__ __half Bsh[32][104];
    __shared__ __half Bsl[32][104];
    __shared__ float stage[8][256];

    int tid = threadIdx.x;
    int wid = tid >> 5;
    int lane = tid & 31;
    int wm = wid & 3;
    int wn = wid >> 2;
    int row0 = blockIdx.x * 128;
    int col0 = blockIdx.y * 96;

    wmma::fragment<wmma::accumulator, 16, 16, 16, float> acc[2][3];
#pragma unroll
    for (int mi = 0; mi < 2; mi++)
#pragma unroll
        for (int ni = 0; ni < 3; ni++) wmma::fill_fragment(acc[mi][ni], 0.0f);

    int nch = Kp >> 5;
    for (int ch = 0; ch < nch; ch++) {
        // A chunk [128 x 32] fp16 (4-half groups)
#pragma unroll
        for (int l = 0; l < 4; l++) {
            int i = tid + l * 256;
            int r = i >> 3, j4 = (i & 7) * 4;
            int grow = row0 + r, gk = ch * 32 + j4;
            uint2 u = make_uint2(0u, 0u);
            if (grow < M && gk < Kphys) {
                u = *(const uint2*)(A + (size_t)grow * Kphys + gk);
                if (IN_RELU) {
                    const __half2* h = (const __half2*)&u;
                    float2 f0 = __half22float2(h[0]);
                    float2 f1 = __half22float2(h[1]);
                    float4 b = *(const float4*)(binA + gk);
                    __half2 o0 = __floats2half2_rn(fmaxf(f0.x + b.x, 0.f), fmaxf(f0.y + b.y, 0.f));
                    __half2 o1 = __floats2half2_rn(fmaxf(f1.x + b.z, 0.f), fmaxf(f1.y + b.w, 0.f));
                    u = make_uint2(*(uint32_t*)&o0, *(uint32_t*)&o1);
                }
            }
            *(uint2*)&Ash[r][j4] = u;
        }
        // B chunk [32 x 96] hi/lo
#pragma unroll
        for (int l = 0; l < 3; l++) {
            int idx = tid + l * 256;
            int k = idx / 24, j4 = (idx - k * 24) * 4;
            size_t src = (size_t)(ch * 32 + k) * Np + col0 + j4;
            *(uint2*)&Bsh[k][j4] = *(const uint2*)(Bhi + src);
            *(uint2*)&Bsl[k][j4] = *(const uint2*)(Blo + src);
        }
        __syncthreads();

#pragma unroll
        for (int kk = 0; kk < 32; kk += 16) {
            wmma::fragment<wmma::matrix_a, 16, 16, 16, __half, wmma::row_major> af[2];
            wmma::fragment<wmma::matrix_b, 16, 16, 16, __half, wmma::row_major> bh[3], bl[3];
#pragma unroll
            for (int mi = 0; mi < 2; mi++)
                wmma::load_matrix_sync(af[mi], &Ash[wm * 32 + mi * 16][kk], 40);
#pragma unroll
            for (int ni = 0; ni < 3; ni++) {
                wmma::load_matrix_sync(bh[ni], &Bsh[kk][wn * 48 + ni * 16], 104);
                wmma::load_matrix_sync(bl[ni], &Bsl[kk][wn * 48 + ni * 16], 104);
            }
#pragma unroll
            for (int mi = 0; mi < 2; mi++)
#pragma unroll
                for (int ni = 0; ni < 3; ni++) {
                    wmma::mma_sync(acc[mi][ni], af[mi], bh[ni], acc[mi][ni]);
                    wmma::mma_sync(acc[mi][ni], af[mi], bl[ni], acc[mi][ni]);
                }
        }
        __syncthreads();
    }

    // epilogue: stage 16x16, bias/relu/scale, fp16 store (4-half groups)
#pragma unroll
    for (int mi = 0; mi < 2; mi++) {
#pragma unroll
        for (int ni = 0; ni < 3; ni++) {
            wmma::store_matrix_sync(stage[wid], acc[mi][ni], 16, wmma::mem_row_major);
            __syncwarp();
            int r = lane >> 1, cg = (lane & 1) * 8;
            int grow = row0 + wm * 32 + mi * 16 + r;
            int col = col0 + wn * 48 + ni * 16 + cg;
            if (grow < M) {
                float s = OUT_SCALE ? dinv[grow] : 1.0f;
                const float* st = &stage[wid][r * 16 + cg];
#pragma unroll
                for (int h4 = 0; h4 < 2; h4++) {
                    int cc = col + h4 * 4;
                    if (cc >= Nd) continue;
                    float f[4];
#pragma unroll
                    for (int j = 0; j < 4; j++) {
                        float v = st[h4 * 4 + j];
                        if (OUT_RELU) v = fmaxf(v + bout[cc + j], 0.0f);
                        if (OUT_SCALE) v *= s;
                        f[j] = v;
                    }
                    sth<4>(C + (size_t)grow * Nd + cc, f);
                }
            }
            __syncwarp();
        }
    }
}

// ---------------------------------------------------------------------------
// FFMA2 GEMM 128x64, double-buffered — conv4 (fp16 in/out, fp32 weights)
// ---------------------------------------------------------------------------
template <bool IN_RELU, bool OUT_SCALE>
__global__ void __launch_bounds__(256)
k_gemm2(const __half* __restrict__ A, int lda, const float* __restrict__ binA,
        const float* __restrict__ B, __half* __restrict__ C,
        const float* __restrict__ dinv, int M, int K, int Nd) {
    __shared__ uint64_t As[2][16][130];
    __shared__ uint64_t Bs[2][16][34];

    int tid = threadIdx.x;
    int tx = tid & 15;
    int ty = tid >> 4;
    int row0 = blockIdx.x * 128;
    int col0 = blockIdx.y * 64;

    uint64_t acc[8][2];
#pragma unroll
    for (int i = 0; i < 8; i++) { acc[i][0] = 0ull; acc[i][1] = 0ull; }

    auto load_tile = [&](int k0, int buf) {
#pragma unroll
        for (int l = 0; l < 8; l++) {
            int idx = tid + l * 256;
            int kk = idx & 15, rr = idx >> 4;
            int grow = row0 + rr, gk = k0 + kk;
            float a = 0.0f;
            if (grow < M && gk < K) {
                a = __half2float(A[(size_t)grow * lda + gk]);
                if (IN_RELU) a = fmaxf(a + binA[gk], 0.0f);
            }
            As[buf][kk][rr] = pack2(a, a);
        }
#pragma unroll
        for (int l = 0; l < 2; l++) {
            int idx = tid + l * 256;
            int cp = idx & 31, kk = idx >> 5;
            int gk = k0 + kk, gc = col0 + 2 * cp;
            float2 bv = make_float2(0.0f, 0.0f);
            if (gk < K && gc < Nd) bv = *(const float2*)(B + (size_t)gk * Nd + gc);
            Bs[buf][kk][cp] = pack2(bv.x, bv.y);
        }
    };

    int nt = (K + 15) >> 4;
    load_tile(0, 0);
    __syncthreads();

    for (int t = 0; t < nt; t++) {
        int buf = t & 1;
        if (t + 1 < nt) load_tile((t + 1) * 16, buf ^ 1);
#pragma unroll
        for (int kk = 0; kk < 16; kk++) {
            ulonglong2 bb = *(const ulonglong2*)&Bs[buf][kk][2 * tx];
#pragma unroll
            for (int i = 0; i < 4; i++) {
                ulonglong2 aa = *(const ulonglong2*)&As[buf][kk][ty * 8 + 2 * i];
                ffma2(acc[2 * i][0],     aa.x, bb.x);
                ffma2(acc[2 * i][1],     aa.x, bb.y);
                ffma2(acc[2 * i + 1][0], aa.y, bb.x);
                ffma2(acc[2 * i + 1][1], aa.y, bb.y);
            }
        }
        __syncthreads();
    }

    int colb = col0 + tx * 4;
#pragma unroll
    for (int i = 0; i < 8; i++) {
        int row = row0 + ty * 8 + i;
        if (row >= M) continue;
        float vv[4];
        unpack2(acc[i][0], vv[0], vv[1]);
        unpack2(acc[i][1], vv[2], vv[3]);
        float s = OUT_SCALE ? dinv[row] : 1.0f;
#pragma unroll
        for (int j2 = 0; j2 < 2; j2++) {
            int col = colb + j2 * 2;
            if (col + 1 >= Nd + 1) continue;
            if (col + 1 < Nd) {
                float f[2] = { vv[j2 * 2] * s, vv[j2 * 2 + 1] * s };
                sth<2>(C + (size_t)row * Nd + col, f);
            } else if (col < Nd) {
                C[(size_t)row * Nd + col] = __float2half_rn(vv[j2 * 2] * s);
            }
        }
    }
}

// ---------------------------------------------------------------------------
// Final fused head: p5 fp16 in, fp32 math, log_softmax out
// ---------------------------------------------------------------------------
__global__ void __launch_bounds__(128)
k_final(const __half* __restrict__ p5,
        const float* __restrict__ Wmu, const float* __restrict__ bmu,
        const float* __restrict__ Wls, const float* __restrict__ bls,
        const float* __restrict__ eps, float* __restrict__ out) {
    __shared__ float sWmu[42 * 21];
    __shared__ float sWls[42 * 21];
    __shared__ float sbmu[21];
    __shared__ float sbls[21];
    for (int i = threadIdx.x; i < 42 * 21; i += blockDim.x) {
        sWmu[i] = Wmu[i];
        sWls[i] = Wls[i];
    }
    if (threadIdx.x < 21) {
        sbmu[threadIdx.x] = bmu[threadIdx.x];
        sbls[threadIdx.x] = bls[threadIdx.x];
    }
    __syncthreads();

    int n = blockIdx.x * blockDim.x + threadIdx.x;
    if (n >= NN) return;

    float xr[42];
#pragma unroll
    for (int i = 0; i < 21; i++) {
        float2 t = __half22float2(*(const __half2*)(p5 + (size_t)n * 42 + 2 * i));
        xr[2 * i] = t.x; xr[2 * i + 1] = t.y;
    }

    float z[21];
#pragma unroll
    for (int j = 0; j < 21; j++) {
        float mu = sbmu[j];
        float ls = sbls[j];
#pragma unroll
        for (int i = 0; i < 42; i++) {
            mu += xr[i] * sWmu[i * 21 + j];
            ls += xr[i] * sWls[i * 21 + j];
        }
        ls = fminf(ls, 10.0f);
        z[j] = mu + eps[(size_t)n * 21 + j] * expf(ls);
    }
    float m = z[0];
#pragma unroll
    for (int j = 1; j < 21; j++) m = fmaxf(m, z[j]);
    float s = 0.0f;
#pragma unroll
    for (int j = 0; j < 21; j++) s += expf(z[j] - m);
    float lse = m + logf(s);
#pragma unroll
    for (int j = 0; j < 21; j++) out[(size_t)n * 21 + j] = z[j] - lse;
}

// ---------------------------------------------------------------------------
static inline int cdiv(long a, long b) { return (int)((a + b - 1) / b); }

extern "C" void kernel_launch(void* const* d_in, const int* in_sizes, int n_in,
                              void* d_out, int out_size) {
    const float* x    = (const float*)d_in[0];
    const int*   ei   = (const int*)  d_in[1];
    const float* eps  = (const float*)d_in[2];
    const float* W1   = (const float*)d_in[3];
    const float* b1   = (const float*)d_in[4];
    const float* W2   = (const float*)d_in[5];
    const float* b2   = (const float*)d_in[6];
    const float* W3   = (const float*)d_in[7];
    const float* b3   = (const float*)d_in[8];
    const float* W4   = (const float*)d_in[9];
    const float* b4   = (const float*)d_in[10];
    const float* Wmu  = (const float*)d_in[11];
    const float* bmu  = (const float*)d_in[12];
    const float* Wls  = (const float*)d_in[13];
    const float* bls  = (const float*)d_in[14];
    float* out = (float*)d_out;

    float* dinv;
    __half *xx, *p0, *a1, *tt2, *p2, *tt3, *p3, *tt4, *a4s, *p5;
    __half *w1hi, *w1lo, *w2hi, *w2lo, *w3hi, *w3lo;
    int *cnt, *cur, *off, *adj, *part;
    cudaGetSymbolAddress((void**)&dinv, g_dinv);
    cudaGetSymbolAddress((void**)&xx,  g_xx);
    cudaGetSymbolAddress((void**)&p0,  g_p0);
    cudaGetSymbolAddress((void**)&a1,  g_a1);
    cudaGetSymbolAddress((void**)&tt2, g_tt2);
    cudaGetSymbolAddress((void**)&p2,  g_p2);
    cudaGetSymbolAddress((void**)&tt3, g_tt3);
    cudaGetSymbolAddress((void**)&p3,  g_p3);
    cudaGetSymbolAddress((void**)&tt4, g_tt4);
    cudaGetSymbolAddress((void**)&a4s, g_a4s);
    cudaGetSymbolAddress((void**)&p5,  g_p5);
    cudaGetSymbolAddress((void**)&w1hi, g_w1hi);
    cudaGetSymbolAddress((void**)&w1lo, g_w1lo);
    cudaGetSymbolAddress((void**)&w2hi, g_w2hi);
    cudaGetSymbolAddress((void**)&w2lo, g_w2lo);
    cudaGetSymbolAddress((void**)&w3hi, g_w3hi);
    cudaGetSymbolAddress((void**)&w3lo, g_w3lo);
    cudaGetSymbolAddress((void**)&cnt, g_cnt);
    cudaGetSymbolAddress((void**)&cur, g_cur);
    cudaGetSymbolAddress((void**)&off, g_off);
    cudaGetSymbolAddress((void**)&adj, g_adj);
    cudaGetSymbolAddress((void**)&part, g_part);

    const int* src = ei;
    const int* dst = ei + EE;

    // ---- CSR build + normalization; weight hi/lo split ----
    k_zero2<<<cdiv(NN, 256), 256>>>(cnt, cur);
    k_count<<<cdiv(EE, 256), 256>>>(dst, cnt);
    k_wsplit<<<cdiv(64 * 384, 256), 256>>>(W1, w1hi, w1lo, 35, 336, 64, 384);
    k_wsplit<<<cdiv(352 * 192, 256), 256>>>(W2, w2hi, w2lo, 336, 168, 352, 192);
    k_wsplit<<<cdiv(192 * 96, 256), 256>>>(W3, w3hi, w3lo, 168, 84, 192, 96);
    k_scan1<<<NPART, 1024>>>(cnt, off, part, dinv);
    k_scan2<<<1, 32>>>(part, off);
    k_scan3<<<NPART, 1024>>>(off, part);
    k_fill<<<cdiv(EE, 256), 256>>>(src, dst, off, cur, adj);

    int gm = cdiv(NN, 128);

    // ---- conv1: aggregate x (D=36), wmma GEMM 35->336 (+b1, relu) ----
    k_pad_scale<<<cdiv((long)NN * 36, 256), 256>>>(x, dinv, xx);
    k_agg<36, 4, false><<<cdiv(NN, 28), 252>>>(off, adj, dinv, xx, nullptr, p0);
    k_wgemm<false, true, false><<<dim3(gm, 4), 256>>>(
        p0, 36, nullptr, w1hi, w1lo, b1, a1, nullptr, NN, 336, 64, 384);

    // ---- conv2: wmma GEMM 336->168 (scaled out), aggregate ----
    k_wgemm<false, false, true><<<dim3(gm, 2), 256>>>(
        a1, 336, nullptr, w2hi, w2lo, nullptr, tt2, dinv, NN, 168, 352, 192);
    k_agg<168, 8, false><<<cdiv(NN, 12), 252>>>(off, adj, dinv, tt2, nullptr, p2);

    // ---- conv3: in = relu(p2+b2), wmma GEMM 168->84, scaled out ----
    k_wgemm<true, false, true><<<dim3(gm, 1), 256>>>(
        p2, 168, b2, w3hi, w3lo, nullptr, tt3, dinv, NN, 84, 192, 96);
    k_agg<84, 4, false><<<cdiv(NN, 12), 252>>>(off, adj, dinv, tt3, nullptr, p3);

    // ---- conv4 (FFMA2): in = relu(p3+b3), 84->42; agg fuses relu+bias ----
    k_gemm2<true, true><<<dim3(gm, 1), 256>>>(
        p3, 84, b3, W4, tt4, dinv, NN, 84, 42);
    k_agg<42, 2, true><<<cdiv(NN, 12), 252>>>(off, adj, dinv, tt4, b4, a4s);

    // ---- shared head propagation ----
    k_agg<42, 2, false><<<cdiv(NN, 12), 252>>>(off, adj, dinv, a4s, nullptr, p5);

    // ---- fused heads + reparam + log_softmax ----
    k_final<<<cdiv(NN, 128), 128>>>(p5, Wmu, bmu, Wls, bls, eps, out);
}

// round 11
// speedup vs baseline: 2.1865x; 1.0282x over previous
#include <cuda_runtime.h>
#include <cuda_fp16.h>
#include <mma.h>
#include <cstdint>

using namespace nvcuda;

#define NN 100000
#define EE 1600000
#define NPART 98   // ceil(NN/1024)

// ---------------------------------------------------------------------------
// Static device scratch — all activations fp16
// ---------------------------------------------------------------------------
__device__ __align__(256) float  g_dinv[NN];
__device__ __align__(256) __half g_xx [NN * 36];
__device__ __align__(256) __half g_p0 [NN * 36];
__device__ __align__(256) __half g_a1 [NN * 336];
__device__ __align__(256) __half g_tt2[NN * 168];
__device__ __align__(256) __half g_p2 [NN * 168];
__device__ __align__(256) __half g_tt3[NN * 84];
__device__ __align__(256) __half g_p3 [NN * 84];
__device__ __align__(256) __half g_tt4[NN * 42];
__device__ __align__(256) __half g_a4s[NN * 42];
__device__ __align__(256) __half g_p5 [NN * 42];

// fp16 weight planes, zero-padded to [Kp][Np]
__device__ __align__(256) __half g_w1[64 * 384];
__device__ __align__(256) __half g_w2[352 * 192];
__device__ __align__(256) __half g_w3[192 * 96];

__device__ __align__(256) int g_cnt[NN];
__device__ __align__(256) int g_cur[NN];
__device__ __align__(256) int g_off[NN + 1];
__device__ __align__(256) int g_adj[EE];
__device__ __align__(256) int g_part[NPART];

// ---------------------------------------------------------------------------
// Packed f32x2 helpers (FFMA2) — conv4 GEMM
// ---------------------------------------------------------------------------
__device__ __forceinline__ uint64_t pack2(float lo, float hi) {
    uint64_t r;
    asm("mov.b64 %0, {%1, %2};" : "=l"(r) : "f"(lo), "f"(hi));
    return r;
}
__device__ __forceinline__ void unpack2(uint64_t v, float& lo, float& hi) {
    asm("mov.b64 {%0, %1}, %2;" : "=f"(lo), "=f"(hi) : "l"(v));
}
__device__ __forceinline__ void ffma2(uint64_t& d, uint64_t a, uint64_t b) {
    asm("fma.rn.f32x2 %0, %1, %2, %3;" : "=l"(d) : "l"(a), "l"(b), "l"(d));
}

// ---------------------------------------------------------------------------
// half vector load/store helpers
// ---------------------------------------------------------------------------
template <int V>
__device__ __forceinline__ void ldh(const __half* p, float* f) {
    if constexpr (V == 8) {
        uint4 u = *(const uint4*)p;
        const __half2* h = (const __half2*)&u;
#pragma unroll
        for (int k = 0; k < 4; k++) {
            float2 t = __half22float2(h[k]);
            f[2 * k] = t.x; f[2 * k + 1] = t.y;
        }
    } else if constexpr (V == 4) {
        uint2 u = *(const uint2*)p;
        const __half2* h = (const __half2*)&u;
#pragma unroll
        for (int k = 0; k < 2; k++) {
            float2 t = __half22float2(h[k]);
            f[2 * k] = t.x; f[2 * k + 1] = t.y;
        }
    } else {
        uint32_t u = *(const uint32_t*)p;
        float2 t = __half22float2(*(const __half2*)&u);
        f[0] = t.x; f[1] = t.y;
    }
}
template <int V>
__device__ __forceinline__ void sth(__half* p, const float* f) {
    if constexpr (V == 8) {
        uint4 u;
        __half2* h = (__half2*)&u;
#pragma unroll
        for (int k = 0; k < 4; k++)
            h[k] = __floats2half2_rn(f[2 * k], f[2 * k + 1]);
        *(uint4*)p = u;
    } else if constexpr (V == 4) {
        uint2 u;
        __half2* h = (__half2*)&u;
#pragma unroll
        for (int k = 0; k < 2; k++)
            h[k] = __floats2half2_rn(f[2 * k], f[2 * k + 1]);
        *(uint2*)p = u;
    } else {
        __half2 h = __floats2half2_rn(f[0], f[1]);
        *(uint32_t*)p = *(uint32_t*)&h;
    }
}

// ---------------------------------------------------------------------------
// CSR build
// ---------------------------------------------------------------------------
__global__ void k_zero2(int* cnt, int* cur) {
    int i = blockIdx.x * blockDim.x + threadIdx.x;
    if (i < NN) { cnt[i] = 0; cur[i] = 0; }
}
__global__ void k_count(const int* __restrict__ dst, int* cnt) {
    int e = blockIdx.x * blockDim.x + threadIdx.x;
    if (e < EE) atomicAdd(&cnt[dst[e]], 1);
}
__global__ void k_scan1(const int* __restrict__ cnt, int* __restrict__ off,
                        int* __restrict__ part, float* __restrict__ dinv) {
    __shared__ int s[1024];
    int t = threadIdx.x;
    int i = blockIdx.x * 1024 + t;
    int v = (i < NN) ? cnt[i] : 0;
    if (i < NN) dinv[i] = rsqrtf((float)v + 1.0f);
    s[t] = v;
    __syncthreads();
    for (int d = 1; d < 1024; d <<= 1) {
        int u = (t >= d) ? s[t - d] : 0;
        __syncthreads();
        s[t] += u;
        __syncthreads();
    }
    if (i < NN) off[i] = s[t] - v;
    if (t == 1023) part[blockIdx.x] = s[1023];
}
// parallel exclusive scan over NPART (<=128) partial sums
__global__ void k_scan2(int* part, int* off) {
    __shared__ int s[128];
    int t = threadIdx.x;
    int v = (t < NPART) ? part[t] : 0;
    s[t] = v;
    __syncthreads();
    for (int d = 1; d < 128; d <<= 1) {
        int u = (t >= d) ? s[t - d] : 0;
        __syncthreads();
        s[t] += u;
        __syncthreads();
    }
    if (t < NPART) part[t] = s[t] - v;   // exclusive
    if (t == 0) off[NN] = EE;
}
__global__ void k_scan3(int* __restrict__ off, const int* __restrict__ part) {
    int i = blockIdx.x * 1024 + threadIdx.x;
    if (i < NN) off[i] += part[blockIdx.x];
}
__global__ void k_fill(const int* __restrict__ src, const int* __restrict__ dst,
                       const int* __restrict__ off, int* cur, int* __restrict__ adj) {
    int e = blockIdx.x * blockDim.x + threadIdx.x;
    if (e >= EE) return;
    int d = dst[e];
    int p = off[d] + atomicAdd(&cur[d], 1);
    adj[p] = src[e];
}

// ---------------------------------------------------------------------------
// xx = fp16(dinv[n] * pad(x))
// ---------------------------------------------------------------------------
__global__ void k_pad_scale(const float* __restrict__ x, const float* __restrict__ dinv,
                            __half* __restrict__ xx) {
    int i = blockIdx.x * blockDim.x + threadIdx.x;
    if (i >= NN * 36) return;
    int n = i / 36, c = i - n * 36;
    float v = (c < 35) ? x[(size_t)n * 35 + c] : 0.0f;
    xx[i] = __float2half_rn(v * dinv[n]);
}

// W [K][Nd] fp32 -> fp16 plane [Kp][Np], zero-padded
__global__ void k_wconv(const float* __restrict__ W, __half* __restrict__ o,
                        int K, int Nd, int Kp, int Np) {
    int i = blockIdx.x * blockDim.x + threadIdx.x;
    if (i >= Kp * Np) return;
    int k = i / Np, n = i - k * Np;
    float v = (k < K && n < Nd) ? W[(size_t)k * Nd + n] : 0.0f;
    o[i] = __float2half_rn(v);
}

// ---------------------------------------------------------------------------
// CSR gather aggregation on fp16 arrays (fp32 accumulate, 4-way unrolled):
//   base: p[d] = fp16(dinv[d] * (tt[d] + sum_{s in N(d)} tt[s]))
//   RBS:  p[d] = fp16(dinv[d] * relu(base + bias[c]))
// ---------------------------------------------------------------------------
template <int D, int V, bool RBS>
__global__ void __launch_bounds__(252)
k_agg(const int* __restrict__ off, const int* __restrict__ adj,
      const float* __restrict__ dinv, const __half* __restrict__ tt,
      const float* __restrict__ bias, __half* __restrict__ p) {
    constexpr int G = D / V;
    constexpr int NPB = 252 / G;
    int g = threadIdx.x / G;
    int c = (threadIdx.x - g * G) * V;
    int node = blockIdx.x * NPB + g;
    if (node >= NN) return;
    int ib = off[node], ie = off[node + 1];
    float acc[V], acc2[V];
    float t0[V], t1[V], t2[V], t3[V];
    ldh<V>(tt + (size_t)node * D + c, acc);
#pragma unroll
    for (int v = 0; v < V; v++) acc2[v] = 0.0f;
    int i = ib;
    for (; i + 4 <= ie; i += 4) {
        int s0 = adj[i], s1 = adj[i + 1], s2 = adj[i + 2], s3 = adj[i + 3];
        ldh<V>(tt + (size_t)s0 * D + c, t0);
        ldh<V>(tt + (size_t)s1 * D + c, t1);
        ldh<V>(tt + (size_t)s2 * D + c, t2);
        ldh<V>(tt + (size_t)s3 * D + c, t3);
#pragma unroll
        for (int v = 0; v < V; v++) {
            acc[v]  += t0[v] + t1[v];
            acc2[v] += t2[v] + t3[v];
        }
    }
    for (; i < ie; i++) {
        int s0 = adj[i];
        ldh<V>(tt + (size_t)s0 * D + c, t0);
#pragma unroll
        for (int v = 0; v < V; v++) acc[v] += t0[v];
    }
    float sc = dinv[node];
#pragma unroll
    for (int v = 0; v < V; v++) {
        float f = (acc[v] + acc2[v]) * sc;
        if (RBS) f = fmaxf(f + bias[c + v], 0.0f) * sc;
        acc[v] = f;
    }
    sth<V>(p + (size_t)node * D + c, acc);
}

// ---------------------------------------------------------------------------
// wmma fp16 GEMM: C = f(A) @ W, A fp16 (exact), W fp16 single plane.
// Block 128x96, 8 warps (4x2), warp tile 32x48. fp32 accumulate.
// ---------------------------------------------------------------------------
template <bool IN_RELU, bool OUT_RELU, bool OUT_SCALE>
__global__ void __launch_bounds__(256)
k_wgemm(const __half* __restrict__ A, int Kphys, const float* __restrict__ binA,
        const __half* __restrict__ B,
        const float* __restrict__ bout, __half* __restrict__ C,
        const float* __restrict__ dinv, int M, int Nd, int Kp, int Np) {
    __shared__ __half Ash[128][40];
    __shared__ __half Bsh[32][104];
    __shared__ float stage[8][256];

    int tid = threadIdx.x;
    int wid = tid >> 5;
    int lane = tid & 31;
    int wm = wid & 3;
    int wn = wid >> 2;
    int row0 = blockIdx.x * 128;
    int col0 = blockIdx.y * 96;

    wmma::fragment<wmma::accumulator, 16, 16, 16, float> acc[2][3];
#pragma unroll
    for (int mi = 0; mi < 2; mi++)
#pragma unroll
        for (int ni = 0; ni < 3; ni++) wmma::fill_fragment(acc[mi][ni], 0.0f);

    int nch = Kp >> 5;
    for (int ch = 0; ch < nch; ch++) {
        // A chunk [128 x 32] fp16 (4-half groups)
#pragma unroll
        for (int l = 0; l < 4; l++) {
            int i = tid + l * 256;
            int r = i >> 3, j4 = (i & 7) * 4;
            int grow = row0 + r, gk = ch * 32 + j4;
            uint2 u = make_uint2(0u, 0u);
            if (grow < M && gk < Kphys) {
                u = *(const uint2*)(A + (size_t)grow * Kphys + gk);
                if (IN_RELU) {
                    const __half2* h = (const __half2*)&u;
                    float2 f0 = __half22float2(h[0]);
                    float2 f1 = __half22float2(h[1]);
                    float4 b = *(const float4*)(binA + gk);
                    __half2 o0 = __floats2half2_rn(fmaxf(f0.x + b.x, 0.f), fmaxf(f0.y + b.y, 0.f));
                    __half2 o1 = __floats2half2_rn(fmaxf(f1.x + b.z, 0.f), fmaxf(f1.y + b.w, 0.f));
                    u = make_uint2(*(uint32_t*)&o0, *(uint32_t*)&o1);
                }
            }
            *(uint2*)&Ash[r][j4] = u;
        }
        // B chunk [32 x 96]
#pragma unroll
        for (int l = 0; l < 3; l++) {
            int idx = tid + l * 256;
            int k = idx / 24, j4 = (idx - k * 24) * 4;
            size_t src = (size_t)(ch * 32 + k) * Np + col0 + j4;
            *(uint2*)&Bsh[k][j4] = *(const uint2*)(B + src);
        }
        __syncthreads();

#pragma unroll
        for (int kk = 0; kk < 32; kk += 16) {
            wmma::fragment<wmma::matrix_a, 16, 16, 16, __half, wmma::row_major> af[2];
            wmma::fragment<wmma::matrix_b, 16, 16, 16, __half, wmma::row_major> bf[3];
#pragma unroll
            for (int mi = 0; mi < 2; mi++)
                wmma::load_matrix_sync(af[mi], &Ash[wm * 32 + mi * 16][kk], 40);
#pragma unroll
            for (int ni = 0; ni < 3; ni++)
                wmma::load_matrix_sync(bf[ni], &Bsh[kk][wn * 48 + ni * 16], 104);
#pragma unroll
            for (int mi = 0; mi < 2; mi++)
#pragma unroll
                for (int ni = 0; ni < 3; ni++)
                    wmma::mma_sync(acc[mi][ni], af[mi], bf[ni], acc[mi][ni]);
        }
        __syncthreads();
    }

    // epilogue: stage 16x16, bias/relu/scale, fp16 store (4-half groups)
#pragma unroll
    for (int mi = 0; mi < 2; mi++) {
#pragma unroll
        for (int ni = 0; ni < 3; ni++) {
            wmma::store_matrix_sync(stage[wid], acc[mi][ni], 16, wmma::mem_row_major);
            __syncwarp();
            int r = lane >> 1, cg = (lane & 1) * 8;
            int grow = row0 + wm * 32 + mi * 16 + r;
            int col = col0 + wn * 48 + ni * 16 + cg;
            if (grow < M) {
                float s = OUT_SCALE ? dinv[grow] : 1.0f;
                const float* st = &stage[wid][r * 16 + cg];
#pragma unroll
                for (int h4 = 0; h4 < 2; h4++) {
                    int cc = col + h4 * 4;
                    if (cc >= Nd) continue;
                    float f[4];
#pragma unroll
                    for (int j = 0; j < 4; j++) {
                        float v = st[h4 * 4 + j];
                        if (OUT_RELU) v = fmaxf(v + bout[cc + j], 0.0f);
                        if (OUT_SCALE) v *= s;
                        f[j] = v;
                    }
                    sth<4>(C + (size_t)grow * Nd + cc, f);
                }
            }
            __syncwarp();
        }
    }
}

// ---------------------------------------------------------------------------
// FFMA2 GEMM 128x64, double-buffered — conv4 (fp16 in/out, fp32 weights)
// ---------------------------------------------------------------------------
template <bool IN_RELU, bool OUT_SCALE>
__global__ void __launch_bounds__(256)
k_gemm2(const __half* __restrict__ A, int lda, const float* __restrict__ binA,
        const float* __restrict__ B, __half* __restrict__ C,
        const float* __restrict__ dinv, int M, int K, int Nd) {
    __shared__ uint64_t As[2][16][130];
    __shared__ uint64_t Bs[2][16][34];

    int tid = threadIdx.x;
    int tx = tid & 15;
    int ty = tid >> 4;
    int row0 = blockIdx.x * 128;
    int col0 = blockIdx.y * 64;

    uint64_t acc[8][2];
#pragma unroll
    for (int i = 0; i < 8; i++) { acc[i][0] = 0ull; acc[i][1] = 0ull; }

    auto load_tile = [&](int k0, int buf) {
#pragma unroll
        for (int l = 0; l < 8; l++) {
            int idx = tid + l * 256;
            int kk = idx & 15, rr = idx >> 4;
            int grow = row0 + rr, gk = k0 + kk;
            float a = 0.0f;
            if (grow < M && gk < K) {
                a = __half2float(A[(size_t)grow * lda + gk]);
                if (IN_RELU) a = fmaxf(a + binA[gk], 0.0f);
            }
            As[buf][kk][rr] = pack2(a, a);
        }
#pragma unroll
        for (int l = 0; l < 2; l++) {
            int idx = tid + l * 256;
            int cp = idx & 31, kk = idx >> 5;
            int gk = k0 + kk, gc = col0 + 2 * cp;
            float2 bv = make_float2(0.0f, 0.0f);
            if (gk < K && gc < Nd) bv = *(const float2*)(B + (size_t)gk * Nd + gc);
            Bs[buf][kk][cp] = pack2(bv.x, bv.y);
        }
    };

    int nt = (K + 15) >> 4;
    load_tile(0, 0);
    __syncthreads();

    for (int t = 0; t < nt; t++) {
        int buf = t & 1;
        if (t + 1 < nt) load_tile((t + 1) * 16, buf ^ 1);
#pragma unroll
        for (int kk = 0; kk < 16; kk++) {
            ulonglong2 bb = *(const ulonglong2*)&Bs[buf][kk][2 * tx];
#pragma unroll
            for (int i = 0; i < 4; i++) {
                ulonglong2 aa = *(const ulonglong2*)&As[buf][kk][ty * 8 + 2 * i];
                ffma2(acc[2 * i][0],     aa.x, bb.x);
                ffma2(acc[2 * i][1],     aa.x, bb.y);
                ffma2(acc[2 * i + 1][0], aa.y, bb.x);
                ffma2(acc[2 * i + 1][1], aa.y, bb.y);
            }
        }
        __syncthreads();
    }

    int colb = col0 + tx * 4;
#pragma unroll
    for (int i = 0; i < 8; i++) {
        int row = row0 + ty * 8 + i;
        if (row >= M) continue;
        float vv[4];
        unpack2(acc[i][0], vv[0], vv[1]);
        unpack2(acc[i][1], vv[2], vv[3]);
        float s = OUT_SCALE ? dinv[row] : 1.0f;
#pragma unroll
        for (int j2 = 0; j2 < 2; j2++) {
            int col = colb + j2 * 2;
            if (col + 1 < Nd) {
                float f[2] = { vv[j2 * 2] * s, vv[j2 * 2 + 1] * s };
                sth<2>(C + (size_t)row * Nd + col, f);
            } else if (col < Nd) {
                C[(size_t)row * Nd + col] = __float2half_rn(vv[j2 * 2] * s);
            }
        }
    }
}

// ---------------------------------------------------------------------------
// Final fused head: p5 fp16 in, fp32 math, log_softmax out
// ---------------------------------------------------------------------------
__global__ void __launch_bounds__(128)
k_final(const __half* __restrict__ p5,
        const float* __restrict__ Wmu, const float* __restrict__ bmu,
        const float* __restrict__ Wls, const float* __restrict__ bls,
        const float* __restrict__ eps, float* __restrict__ out) {
    __shared__ float sWmu[42 * 21];
    __shared__ float sWls[42 * 21];
    __shared__ float sbmu[21];
    __shared__ float sbls[21];
    for (int i = threadIdx.x; i < 42 * 21; i += blockDim.x) {
        sWmu[i] = Wmu[i];
        sWls[i] = Wls[i];
    }
    if (threadIdx.x < 21) {
        sbmu[threadIdx.x] = bmu[threadIdx.x];
        sbls[threadIdx.x] = bls[threadIdx.x];
    }
    __syncthreads();

    int n = blockIdx.x * blockDim.x + threadIdx.x;
    if (n >= NN) return;

    float xr[42];
#pragma unroll
    for (int i = 0; i < 21; i++) {
        float2 t = __half22float2(*(const __half2*)(p5 + (size_t)n * 42 + 2 * i));
        xr[2 * i] = t.x; xr[2 * i + 1] = t.y;
    }

    float z[21];
#pragma unroll
    for (int j = 0; j < 21; j++) {
        float mu = sbmu[j];
        float ls = sbls[j];
#pragma unroll
        for (int i = 0; i < 42; i++) {
            mu += xr[i] * sWmu[i * 21 + j];
            ls += xr[i] * sWls[i * 21 + j];
        }
        ls = fminf(ls, 10.0f);
        z[j] = mu + eps[(size_t)n * 21 + j] * expf(ls);
    }
    float m = z[0];
#pragma unroll
    for (int j = 1; j < 21; j++) m = fmaxf(m, z[j]);
    float s = 0.0f;
#pragma unroll
    for (int j = 0; j < 21; j++) s += expf(z[j] - m);
    float lse = m + logf(s);
#pragma unroll
    for (int j = 0; j < 21; j++) out[(size_t)n * 21 + j] = z[j] - lse;
}

// ---------------------------------------------------------------------------
static inline int cdiv(long a, long b) { return (int)((a + b - 1) / b); }

extern "C" void kernel_launch(void* const* d_in, const int* in_sizes, int n_in,
                              void* d_out, int out_size) {
    const float* x    = (const float*)d_in[0];
    const int*   ei   = (const int*)  d_in[1];
    const float* eps  = (const float*)d_in[2];
    const float* W1   = (const float*)d_in[3];
    const float* b1   = (const float*)d_in[4];
    const float* W2   = (const float*)d_in[5];
    const float* b2   = (const float*)d_in[6];
    const float* W3   = (const float*)d_in[7];
    const float* b3   = (const float*)d_in[8];
    const float* W4   = (const float*)d_in[9];
    const float* b4   = (const float*)d_in[10];
    const float* Wmu  = (const float*)d_in[11];
    const float* bmu  = (const float*)d_in[12];
    const float* Wls  = (const float*)d_in[13];
    const float* bls  = (const float*)d_in[14];
    float* out = (float*)d_out;

    float* dinv;
    __half *xx, *p0, *a1, *tt2, *p2, *tt3, *p3, *tt4, *a4s, *p5;
    __half *w1, *w2, *w3;
    int *cnt, *cur, *off, *adj, *part;
    cudaGetSymbolAddress((void**)&dinv, g_dinv);
    cudaGetSymbolAddress((void**)&xx,  g_xx);
    cudaGetSymbolAddress((void**)&p0,  g_p0);
    cudaGetSymbolAddress((void**)&a1,  g_a1);
    cudaGetSymbolAddress((void**)&tt2, g_tt2);
    cudaGetSymbolAddress((void**)&p2,  g_p2);
    cudaGetSymbolAddress((void**)&tt3, g_tt3);
    cudaGetSymbolAddress((void**)&p3,  g_p3);
    cudaGetSymbolAddress((void**)&tt4, g_tt4);
    cudaGetSymbolAddress((void**)&a4s, g_a4s);
    cudaGetSymbolAddress((void**)&p5,  g_p5);
    cudaGetSymbolAddress((void**)&w1, g_w1);
    cudaGetSymbolAddress((void**)&w2, g_w2);
    cudaGetSymbolAddress((void**)&w3, g_w3);
    cudaGetSymbolAddress((void**)&cnt, g_cnt);
    cudaGetSymbolAddress((void**)&cur, g_cur);
    cudaGetSymbolAddress((void**)&off, g_off);
    cudaGetSymbolAddress((void**)&adj, g_adj);
    cudaGetSymbolAddress((void**)&part, g_part);

    const int* src = ei;
    const int* dst = ei + EE;

    // ---- CSR build + normalization; weight fp16 prep ----
    k_zero2<<<cdiv(NN, 256), 256>>>(cnt, cur);
    k_count<<<cdiv(EE, 256), 256>>>(dst, cnt);
    k_wconv<<<cdiv(64 * 384, 256), 256>>>(W1, w1, 35, 336, 64, 384);
    k_wconv<<<cdiv(352 * 192, 256), 256>>>(W2, w2, 336, 168, 352, 192);
    k_wconv<<<cdiv(192 * 96, 256), 256>>>(W3, w3, 168, 84, 192, 96);
    k_scan1<<<NPART, 1024>>>(cnt, off, part, dinv);
    k_scan2<<<1, 128>>>(part, off);
    k_scan3<<<NPART, 1024>>>(off, part);
    k_fill<<<cdiv(EE, 256), 256>>>(src, dst, off, cur, adj);

    int gm = cdiv(NN, 128);

    // ---- conv1: aggregate x (D=36), wmma GEMM 35->336 (+b1, relu) ----
    k_pad_scale<<<cdiv((long)NN * 36, 256), 256>>>(x, dinv, xx);
    k_agg<36, 4, false><<<cdiv(NN, 28), 252>>>(off, adj, dinv, xx, nullptr, p0);
    k_wgemm<false, true, false><<<dim3(gm, 4), 256>>>(
        p0, 36, nullptr, w1, b1, a1, nullptr, NN, 336, 64, 384);

    // ---- conv2: wmma GEMM 336->168 (scaled out), aggregate ----
    k_wgemm<false, false, true><<<dim3(gm, 2), 256>>>(
        a1, 336, nullptr, w2, nullptr, tt2, dinv, NN, 168, 352, 192);
    k_agg<168, 8, false><<<cdiv(NN, 12), 252>>>(off, adj, dinv, tt2, nullptr, p2);

    // ---- conv3: in = relu(p2+b2), wmma GEMM 168->84, scaled out ----
    k_wgemm<true, false, true><<<dim3(gm, 1), 256>>>(
        p2, 168, b2, w3, nullptr, tt3, dinv, NN, 84, 192, 96);
    k_agg<84, 4, false><<<cdiv(NN, 12), 252>>>(off, adj, dinv, tt3, nullptr, p3);

    // ---- conv4 (FFMA2): in = relu(p3+b3), 84->42; agg fuses relu+bias ----
    k_gemm2<true, true><<<dim3(gm, 1), 256>>>(
        p3, 84, b3, W4, tt4, dinv, NN, 84, 42);
    k_agg<42, 2, true><<<cdiv(NN, 12), 252>>>(off, adj, dinv, tt4, b4, a4s);

    // ---- shared head propagation ----
    k_agg<42, 2, false><<<cdiv(NN, 12), 252>>>(off, adj, dinv, a4s, nullptr, p5);

    // ---- fused heads + reparam + log_softmax ----
    k_final<<<cdiv(NN, 128), 128>>>(p5, Wmu, bmu, Wls, bls, eps, out);
}

// round 13
// speedup vs baseline: 2.2934x; 1.0489x over previous
#include <cuda_runtime.h>
#include <cuda_fp16.h>
#include <mma.h>
#include <cstdint>

using namespace nvcuda;

#define NN 100000
#define EE 1600000
#define NPART 98   // ceil(NN/1024)

// ---------------------------------------------------------------------------
// Static device scratch — all activations fp16
// ---------------------------------------------------------------------------
__device__ __align__(256) float  g_dinv[NN];
__device__ __align__(256) __half g_xx [NN * 36];
__device__ __align__(256) __half g_p0 [NN * 36];
__device__ __align__(256) __half g_a1 [NN * 336];
__device__ __align__(256) __half g_tt2[NN * 168];
__device__ __align__(256) __half g_p2 [NN * 168];
__device__ __align__(256) __half g_tt3[NN * 84];
__device__ __align__(256) __half g_p3 [NN * 84];
__device__ __align__(256) __half g_tt4[NN * 42];
__device__ __align__(256) __half g_a4s[NN * 42];
__device__ __align__(256) __half g_p5 [NN * 42];

// fp16 weight planes, zero-padded to [Kp][Np]
__device__ __align__(256) __half g_w1[64 * 384];
__device__ __align__(256) __half g_w2[352 * 192];
__device__ __align__(256) __half g_w3[192 * 96];
__device__ __align__(256) __half g_w4[96 * 96];

__device__ __align__(256) int g_cnt[NN];
__device__ __align__(256) int g_off[NN + 1];
__device__ __align__(256) int g_adj[EE];
__device__ __align__(256) int g_part[NPART];

// ---------------------------------------------------------------------------
// half vector load/store helpers
// ---------------------------------------------------------------------------
template <int V>
__device__ __forceinline__ void ldh(const __half* p, float* f) {
    if constexpr (V == 8) {
        uint4 u = *(const uint4*)p;
        const __half2* h = (const __half2*)&u;
#pragma unroll
        for (int k = 0; k < 4; k++) {
            float2 t = __half22float2(h[k]);
            f[2 * k] = t.x; f[2 * k + 1] = t.y;
        }
    } else if constexpr (V == 4) {
        uint2 u = *(const uint2*)p;
        const __half2* h = (const __half2*)&u;
#pragma unroll
        for (int k = 0; k < 2; k++) {
            float2 t = __half22float2(h[k]);
            f[2 * k] = t.x; f[2 * k + 1] = t.y;
        }
    } else {
        uint32_t u = *(const uint32_t*)p;
        float2 t = __half22float2(*(const __half2*)&u);
        f[0] = t.x; f[1] = t.y;
    }
}
template <int V>
__device__ __forceinline__ void sth(__half* p, const float* f) {
    if constexpr (V == 8) {
        uint4 u;
        __half2* h = (__half2*)&u;
#pragma unroll
        for (int k = 0; k < 4; k++)
            h[k] = __floats2half2_rn(f[2 * k], f[2 * k + 1]);
        *(uint4*)p = u;
    } else if constexpr (V == 4) {
        uint2 u;
        __half2* h = (__half2*)&u;
#pragma unroll
        for (int k = 0; k < 2; k++)
            h[k] = __floats2half2_rn(f[2 * k], f[2 * k + 1]);
        *(uint2*)p = u;
    } else {
        __half2 h = __floats2half2_rn(f[0], f[1]);
        *(uint32_t*)p = *(uint32_t*)&h;
    }
}

// ---------------------------------------------------------------------------
// Fused prep: zero cnt, off[NN]=EE, convert W1..W4 to fp16 padded planes.
// MUST be launched with >= max(NN, W1N+W2N+W3N+W4N) threads.
// ---------------------------------------------------------------------------
__device__ __forceinline__ void wcvt(const float* W, __half* o, int j,
                                     int K, int Nd, int Np) {
    int k = j / Np, n = j - k * Np;
    float v = (k < K && n < Nd) ? W[(size_t)k * Nd + n] : 0.0f;
    o[j] = __float2half_rn(v);
}
#define W1N (64 * 384)
#define W2N (352 * 192)
#define W3N (192 * 96)
#define W4N (96 * 96)
#define WTOT (W1N + W2N + W3N + W4N)
__global__ void k_prep(const float* __restrict__ W1, const float* __restrict__ W2,
                       const float* __restrict__ W3, const float* __restrict__ W4,
                       __half* __restrict__ w1, __half* __restrict__ w2,
                       __half* __restrict__ w3, __half* __restrict__ w4,
                       int* __restrict__ cnt, int* __restrict__ off) {
    int i = blockIdx.x * blockDim.x + threadIdx.x;
    if (i == 0) off[NN] = EE;
    if (i < NN) cnt[i] = 0;
    if (i < W1N) wcvt(W1, w1, i, 35, 336, 384);
    else if (i < W1N + W2N) wcvt(W2, w2, i - W1N, 336, 168, 192);
    else if (i < W1N + W2N + W3N) wcvt(W3, w3, i - W1N - W2N, 168, 84, 96);
    else if (i < WTOT) wcvt(W4, w4, i - W1N - W2N - W3N, 84, 42, 96);
}

// ---------------------------------------------------------------------------
// CSR build
// ---------------------------------------------------------------------------
__global__ void k_count(const int* __restrict__ dst, int* cnt) {
    int e = blockIdx.x * blockDim.x + threadIdx.x;
    if (e < EE) atomicAdd(&cnt[dst[e]], 1);
}
__global__ void k_scan1(const int* __restrict__ cnt, int* __restrict__ off,
                        int* __restrict__ part, float* __restrict__ dinv) {
    __shared__ int s[1024];
    int t = threadIdx.x;
    int i = blockIdx.x * 1024 + t;
    int v = (i < NN) ? cnt[i] : 0;
    if (i < NN) dinv[i] = rsqrtf((float)v + 1.0f);
    s[t] = v;
    __syncthreads();
    for (int d = 1; d < 1024; d <<= 1) {
        int u = (t >= d) ? s[t - d] : 0;
        __syncthreads();
        s[t] += u;
        __syncthreads();
    }
    if (i < NN) off[i] = s[t] - v;          // block-local exclusive
    if (t == 1023) part[blockIdx.x] = s[1023];
}
// scan3 with fused partial-sum scan (each block scans the 98 partials itself)
__global__ void k_scan3(int* __restrict__ off, const int* __restrict__ part) {
    __shared__ int s[128];
    int t = threadIdx.x;
    if (t < 128) s[t] = (t < NPART) ? part[t] : 0;
    __syncthreads();
    for (int d = 1; d < 128; d <<= 1) {
        int u = 0;
        if (t < 128 && t >= d) u = s[t - d];
        __syncthreads();
        if (t < 128) s[t] += u;
        __syncthreads();
    }
    int base = (blockIdx.x > 0) ? s[blockIdx.x - 1] : 0;   // exclusive prefix
    int i = blockIdx.x * 1024 + t;
    if (i < NN) off[i] += base;
}
// fill reusing cnt via atomic decrement (cnt destroyed; dinv already extracted)
__global__ void k_fill(const int* __restrict__ src, const int* __restrict__ dst,
                       const int* __restrict__ off, int* cnt, int* __restrict__ adj) {
    int e = blockIdx.x * blockDim.x + threadIdx.x;
    if (e >= EE) return;
    int d = dst[e];
    int p = off[d] + atomicAdd(&cnt[d], -1) - 1;
    adj[p] = src[e];
}

// ---------------------------------------------------------------------------
// xx = fp16(dinv[n] * pad(x))
// ---------------------------------------------------------------------------
__global__ void k_pad_scale(const float* __restrict__ x, const float* __restrict__ dinv,
                            __half* __restrict__ xx) {
    int i = blockIdx.x * blockDim.x + threadIdx.x;
    if (i >= NN * 36) return;
    int n = i / 36, c = i - n * 36;
    float v = (c < 35) ? x[(size_t)n * 35 + c] : 0.0f;
    xx[i] = __float2half_rn(v * dinv[n]);
}

// ---------------------------------------------------------------------------
// CSR gather aggregation on fp16 arrays (fp32 accumulate, 4-way unrolled)
// ---------------------------------------------------------------------------
template <int D, int V, bool RBS>
__global__ void __launch_bounds__(252)
k_agg(const int* __restrict__ off, const int* __restrict__ adj,
      const float* __restrict__ dinv, const __half* __restrict__ tt,
      const float* __restrict__ bias, __half* __restrict__ p) {
    constexpr int G = D / V;
    constexpr int NPB = 252 / G;
    int g = threadIdx.x / G;
    int c = (threadIdx.x - g * G) * V;
    int node = blockIdx.x * NPB + g;
    if (node >= NN) return;
    int ib = off[node], ie = off[node + 1];
    float acc[V], acc2[V];
    float t0[V], t1[V], t2[V], t3[V];
    ldh<V>(tt + (size_t)node * D + c, acc);
#pragma unroll
    for (int v = 0; v < V; v++) acc2[v] = 0.0f;
    int i = ib;
    for (; i + 4 <= ie; i += 4) {
        int s0 = adj[i], s1 = adj[i + 1], s2 = adj[i + 2], s3 = adj[i + 3];
        ldh<V>(tt + (size_t)s0 * D + c, t0);
        ldh<V>(tt + (size_t)s1 * D + c, t1);
        ldh<V>(tt + (size_t)s2 * D + c, t2);
        ldh<V>(tt + (size_t)s3 * D + c, t3);
#pragma unroll
        for (int v = 0; v < V; v++) {
            acc[v]  += t0[v] + t1[v];
            acc2[v] += t2[v] + t3[v];
        }
    }
    for (; i < ie; i++) {
        int s0 = adj[i];
        ldh<V>(tt + (size_t)s0 * D + c, t0);
#pragma unroll
        for (int v = 0; v < V; v++) acc[v] += t0[v];
    }
    float sc = dinv[node];
#pragma unroll
    for (int v = 0; v < V; v++) {
        float f = (acc[v] + acc2[v]) * sc;
        if (RBS) f = fmaxf(f + bias[c + v], 0.0f) * sc;
        acc[v] = f;
    }
    sth<V>(p + (size_t)node * D + c, acc);
}

// ---------------------------------------------------------------------------
// wmma fp16 GEMM: C = f(A) @ W. Block 128x96, 8 warps (4x2), warp 32x48.
// fp32 accumulate. Alignment-safe epilogue for Nd % 4 != 0 (half2 stores).
// ---------------------------------------------------------------------------
template <bool IN_RELU, bool OUT_RELU, bool OUT_SCALE>
__global__ void __launch_bounds__(256)
k_wgemm(const __half* __restrict__ A, int Kphys, const float* __restrict__ binA,
        const __half* __restrict__ B,
        const float* __restrict__ bout, __half* __restrict__ C,
        const float* __restrict__ dinv, int M, int Nd, int Kp, int Np) {
    __shared__ __half Ash[128][40];
    __shared__ __half Bsh[32][104];
    __shared__ float stage[8][256];

    int tid = threadIdx.x;
    int wid = tid >> 5;
    int lane = tid & 31;
    int wm = wid & 3;
    int wn = wid >> 2;
    int row0 = blockIdx.x * 128;
    int col0 = blockIdx.y * 96;
    bool al8 = ((Nd & 3) == 0);

    wmma::fragment<wmma::accumulator, 16, 16, 16, float> acc[2][3];
#pragma unroll
    for (int mi = 0; mi < 2; mi++)
#pragma unroll
        for (int ni = 0; ni < 3; ni++) wmma::fill_fragment(acc[mi][ni], 0.0f);

    int nch = Kp >> 5;
    for (int ch = 0; ch < nch; ch++) {
        // A chunk [128 x 32] fp16 (4-half groups)
#pragma unroll
        for (int l = 0; l < 4; l++) {
            int i = tid + l * 256;
            int r = i >> 3, j4 = (i & 7) * 4;
            int grow = row0 + r, gk = ch * 32 + j4;
            uint2 u = make_uint2(0u, 0u);
            if (grow < M && gk < Kphys) {
                u = *(const uint2*)(A + (size_t)grow * Kphys + gk);
                if (IN_RELU) {
                    const __half2* h = (const __half2*)&u;
                    float2 f0 = __half22float2(h[0]);
                    float2 f1 = __half22float2(h[1]);
                    float4 b = *(const float4*)(binA + gk);
                    __half2 o0 = __floats2half2_rn(fmaxf(f0.x + b.x, 0.f), fmaxf(f0.y + b.y, 0.f));
                    __half2 o1 = __floats2half2_rn(fmaxf(f1.x + b.z, 0.f), fmaxf(f1.y + b.w, 0.f));
                    u = make_uint2(*(uint32_t*)&o0, *(uint32_t*)&o1);
                }
            }
            *(uint2*)&Ash[r][j4] = u;
        }
        // B chunk [32 x 96]
#pragma unroll
        for (int l = 0; l < 3; l++) {
            int idx = tid + l * 256;
            int k = idx / 24, j4 = (idx - k * 24) * 4;
            size_t src = (size_t)(ch * 32 + k) * Np + col0 + j4;
            *(uint2*)&Bsh[k][j4] = *(const uint2*)(B + src);
        }
        __syncthreads();

#pragma unroll
        for (int kk = 0; kk < 32; kk += 16) {
            wmma::fragment<wmma::matrix_a, 16, 16, 16, __half, wmma::row_major> af[2];
            wmma::fragment<wmma::matrix_b, 16, 16, 16, __half, wmma::row_major> bf[3];
#pragma unroll
            for (int mi = 0; mi < 2; mi++)
                wmma::load_matrix_sync(af[mi], &Ash[wm * 32 + mi * 16][kk], 40);
#pragma unroll
            for (int ni = 0; ni < 3; ni++)
                wmma::load_matrix_sync(bf[ni], &Bsh[kk][wn * 48 + ni * 16], 104);
#pragma unroll
            for (int mi = 0; mi < 2; mi++)
#pragma unroll
                for (int ni = 0; ni < 3; ni++)
                    wmma::mma_sync(acc[mi][ni], af[mi], bf[ni], acc[mi][ni]);
        }
        __syncthreads();
    }

    // epilogue
#pragma unroll
    for (int mi = 0; mi < 2; mi++) {
#pragma unroll
        for (int ni = 0; ni < 3; ni++) {
            wmma::store_matrix_sync(stage[wid], acc[mi][ni], 16, wmma::mem_row_major);
            __syncwarp();
            int r = lane >> 1, cg = (lane & 1) * 8;
            int grow = row0 + wm * 32 + mi * 16 + r;
            int col = col0 + wn * 48 + ni * 16 + cg;
            if (grow < M) {
                float s = OUT_SCALE ? dinv[grow] : 1.0f;
                const float* st = &stage[wid][r * 16 + cg];
#pragma unroll
                for (int h4 = 0; h4 < 2; h4++) {
                    int cc = col + h4 * 4;
                    if (cc >= Nd) continue;
                    float f[4];
#pragma unroll
                    for (int j = 0; j < 4; j++) {
                        float v = st[h4 * 4 + j];
                        if (OUT_RELU) v = fmaxf(v + bout[cc + j], 0.0f);
                        if (OUT_SCALE) v *= s;
                        f[j] = v;
                    }
                    __half* dst = C + (size_t)grow * Nd + cc;
                    if (al8 && cc + 4 <= Nd) {
                        sth<4>(dst, f);
                    } else {
                        int nw = Nd - cc; if (nw > 4) nw = 4;
                        for (int j = 0; j + 2 <= nw; j += 2) sth<2>(dst + j, f + j);
                    }
                }
            }
            __syncwarp();
        }
    }
}

// ---------------------------------------------------------------------------
// Final fused head: p5 fp16 in, fp32 math, log_softmax out
// ---------------------------------------------------------------------------
__global__ void __launch_bounds__(128)
k_final(const __half* __restrict__ p5,
        const float* __restrict__ Wmu, const float* __restrict__ bmu,
        const float* __restrict__ Wls, const float* __restrict__ bls,
        const float* __restrict__ eps, float* __restrict__ out) {
    __shared__ float sWmu[42 * 21];
    __shared__ float sWls[42 * 21];
    __shared__ float sbmu[21];
    __shared__ float sbls[21];
    for (int i = threadIdx.x; i < 42 * 21; i += blockDim.x) {
        sWmu[i] = Wmu[i];
        sWls[i] = Wls[i];
    }
    if (threadIdx.x < 21) {
        sbmu[threadIdx.x] = bmu[threadIdx.x];
        sbls[threadIdx.x] = bls[threadIdx.x];
    }
    __syncthreads();

    int n = blockIdx.x * blockDim.x + threadIdx.x;
    if (n >= NN) return;

    float xr[42];
#pragma unroll
    for (int i = 0; i < 21; i++) {
        float2 t = __half22float2(*(const __half2*)(p5 + (size_t)n * 42 + 2 * i));
        xr[2 * i] = t.x; xr[2 * i + 1] = t.y;
    }

    float z[21];
#pragma unroll
    for (int j = 0; j < 21; j++) {
        float mu = sbmu[j];
        float ls = sbls[j];
#pragma unroll
        for (int i = 0; i < 42; i++) {
            mu += xr[i] * sWmu[i * 21 + j];
            ls += xr[i] * sWls[i * 21 + j];
        }
        ls = fminf(ls, 10.0f);
        z[j] = mu + eps[(size_t)n * 21 + j] * expf(ls);
    }
    float m = z[0];
#pragma unroll
    for (int j = 1; j < 21; j++) m = fmaxf(m, z[j]);
    float s = 0.0f;
#pragma unroll
    for (int j = 0; j < 21; j++) s += expf(z[j] - m);
    float lse = m + logf(s);
#pragma unroll
    for (int j = 0; j < 21; j++) out[(size_t)n * 21 + j] = z[j] - lse;
}

// ---------------------------------------------------------------------------
static inline int cdiv(long a, long b) { return (int)((a + b - 1) / b); }

extern "C" void kernel_launch(void* const* d_in, const int* in_sizes, int n_in,
                              void* d_out, int out_size) {
    const float* x    = (const float*)d_in[0];
    const int*   ei   = (const int*)  d_in[1];
    const float* eps  = (const float*)d_in[2];
    const float* W1   = (const float*)d_in[3];
    const float* b1   = (const float*)d_in[4];
    const float* W2   = (const float*)d_in[5];
    const float* b2   = (const float*)d_in[6];
    const float* W3   = (const float*)d_in[7];
    const float* b3   = (const float*)d_in[8];
    const float* W4   = (const float*)d_in[9];
    const float* b4   = (const float*)d_in[10];
    const float* Wmu  = (const float*)d_in[11];
    const float* bmu  = (const float*)d_in[12];
    const float* Wls  = (const float*)d_in[13];
    const float* bls  = (const float*)d_in[14];
    float* out = (float*)d_out;

    float* dinv;
    __half *xx, *p0, *a1, *tt2, *p2, *tt3, *p3, *tt4, *a4s, *p5;
    __half *w1, *w2, *w3, *w4;
    int *cnt, *off, *adj, *part;
    cudaGetSymbolAddress((void**)&dinv, g_dinv);
    cudaGetSymbolAddress((void**)&xx,  g_xx);
    cudaGetSymbolAddress((void**)&p0,  g_p0);
    cudaGetSymbolAddress((void**)&a1,  g_a1);
    cudaGetSymbolAddress((void**)&tt2, g_tt2);
    cudaGetSymbolAddress((void**)&p2,  g_p2);
    cudaGetSymbolAddress((void**)&tt3, g_tt3);
    cudaGetSymbolAddress((void**)&p3,  g_p3);
    cudaGetSymbolAddress((void**)&tt4, g_tt4);
    cudaGetSymbolAddress((void**)&a4s, g_a4s);
    cudaGetSymbolAddress((void**)&p5,  g_p5);
    cudaGetSymbolAddress((void**)&w1, g_w1);
    cudaGetSymbolAddress((void**)&w2, g_w2);
    cudaGetSymbolAddress((void**)&w3, g_w3);
    cudaGetSymbolAddress((void**)&w4, g_w4);
    cudaGetSymbolAddress((void**)&cnt, g_cnt);
    cudaGetSymbolAddress((void**)&off, g_off);
    cudaGetSymbolAddress((void**)&adj, g_adj);
    cudaGetSymbolAddress((void**)&part, g_part);

    const int* src = ei;
    const int* dst = ei + EE;

    // ---- fused prep + CSR build ----
    long prep_n = (long)NN > (long)WTOT ? (long)NN : (long)WTOT;
    k_prep<<<cdiv(prep_n, 256), 256>>>(W1, W2, W3, W4, w1, w2, w3, w4, cnt, off);
    k_count<<<cdiv(EE, 256), 256>>>(dst, cnt);
    k_scan1<<<NPART, 1024>>>(cnt, off, part, dinv);
    k_scan3<<<NPART, 1024>>>(off, part);
    k_fill<<<cdiv(EE, 256), 256>>>(src, dst, off, cnt, adj);

    int gm = cdiv(NN, 128);

    // ---- conv1: aggregate x (D=36), wmma GEMM 35->336 (+b1, relu) ----
    k_pad_scale<<<cdiv((long)NN * 36, 256), 256>>>(x, dinv, xx);
    k_agg<36, 4, false><<<cdiv(NN, 28), 252>>>(off, adj, dinv, xx, nullptr, p0);
    k_wgemm<false, true, false><<<dim3(gm, 4), 256>>>(
        p0, 36, nullptr, w1, b1, a1, nullptr, NN, 336, 64, 384);

    // ---- conv2: wmma GEMM 336->168 (scaled out), aggregate ----
    k_wgemm<false, false, true><<<dim3(gm, 2), 256>>>(
        a1, 336, nullptr, w2, nullptr, tt2, dinv, NN, 168, 352, 192);
    k_agg<168, 8, false><<<cdiv(NN, 12), 252>>>(off, adj, dinv, tt2, nullptr, p2);

    // ---- conv3: in = relu(p2+b2), wmma GEMM 168->84, scaled out ----
    k_wgemm<true, false, true><<<dim3(gm, 1), 256>>>(
        p2, 168, b2, w3, nullptr, tt3, dinv, NN, 84, 192, 96);
    k_agg<84, 4, false><<<cdiv(NN, 12), 252>>>(off, adj, dinv, tt3, nullptr, p3);

    // ---- conv4: in = relu(p3+b3), wmma GEMM 84->42, scaled out ----
    k_wgemm<true, false, true><<<dim3(gm, 1), 256>>>(
        p3, 84, b3, w4, nullptr, tt4, dinv, NN, 42, 96, 96);
    k_agg<42, 2, true><<<cdiv(NN, 12), 252>>>(off, adj, dinv, tt4, b4, a4s);

    // ---- shared head propagation ----
    k_agg<42, 2, false><<<cdiv(NN, 12), 252>>>(off, adj, dinv, a4s, nullptr, p5);

    // ---- fused heads + reparam + log_softmax ----
    k_final<<<cdiv(NN, 128), 128>>>(p5, Wmu, bmu, Wls, bls, eps, out);
}

// round 14
// speedup vs baseline: 2.3924x; 1.0432x over previous
#include <cuda_runtime.h>
#include <cuda_fp16.h>
#include <mma.h>
#include <cstdint>

using namespace nvcuda;

#define NN 100000
#define EE 1600000
#define NPART 98   // ceil(NN/1024)

// ---------------------------------------------------------------------------
// Static device scratch — all activations fp16
// ---------------------------------------------------------------------------
__device__ __align__(256) float  g_dinv[NN];
__device__ __align__(256) __half g_xx [NN * 36];
__device__ __align__(256) __half g_p0 [NN * 36];
__device__ __align__(256) __half g_a1 [NN * 336];
__device__ __align__(256) __half g_tt2[NN * 168];
__device__ __align__(256) __half g_p2 [NN * 168];
__device__ __align__(256) __half g_tt3[NN * 84];
__device__ __align__(256) __half g_p3 [NN * 84];
__device__ __align__(256) __half g_tt4[NN * 42];
__device__ __align__(256) __half g_a4s[NN * 42];
__device__ __align__(256) __half g_p5 [NN * 42];

// fp16 weight planes, zero-padded to [Kp][Np]
__device__ __align__(256) __half g_w1[64 * 384];
__device__ __align__(256) __half g_w2[352 * 192];
__device__ __align__(256) __half g_w3[192 * 96];
__device__ __align__(256) __half g_w4[96 * 96];

__device__ __align__(256) int g_cnt[NN];
__device__ __align__(256) int g_off[NN + 1];
__device__ __align__(256) int g_adj[EE];
__device__ __align__(256) int g_part[NPART];

// ---------------------------------------------------------------------------
// half vector load/store helpers
// ---------------------------------------------------------------------------
template <int V>
__device__ __forceinline__ void ldh(const __half* p, float* f) {
    if constexpr (V == 8) {
        uint4 u = *(const uint4*)p;
        const __half2* h = (const __half2*)&u;
#pragma unroll
        for (int k = 0; k < 4; k++) {
            float2 t = __half22float2(h[k]);
            f[2 * k] = t.x; f[2 * k + 1] = t.y;
        }
    } else if constexpr (V == 4) {
        uint2 u = *(const uint2*)p;
        const __half2* h = (const __half2*)&u;
#pragma unroll
        for (int k = 0; k < 2; k++) {
            float2 t = __half22float2(h[k]);
            f[2 * k] = t.x; f[2 * k + 1] = t.y;
        }
    } else {
        uint32_t u = *(const uint32_t*)p;
        float2 t = __half22float2(*(const __half2*)&u);
        f[0] = t.x; f[1] = t.y;
    }
}
template <int V>
__device__ __forceinline__ void sth(__half* p, const float* f) {
    if constexpr (V == 8) {
        uint4 u;
        __half2* h = (__half2*)&u;
#pragma unroll
        for (int k = 0; k < 4; k++)
            h[k] = __floats2half2_rn(f[2 * k], f[2 * k + 1]);
        *(uint4*)p = u;
    } else if constexpr (V == 4) {
        uint2 u;
        __half2* h = (__half2*)&u;
#pragma unroll
        for (int k = 0; k < 2; k++)
            h[k] = __floats2half2_rn(f[2 * k], f[2 * k + 1]);
        *(uint2*)p = u;
    } else {
        __half2 h = __floats2half2_rn(f[0], f[1]);
        *(uint32_t*)p = *(uint32_t*)&h;
    }
}

// ---------------------------------------------------------------------------
// Fused prep: zero cnt, off[NN]=EE, convert W1..W4 to fp16 padded planes.
// Launched with >= max(NN, WTOT) threads.
// ---------------------------------------------------------------------------
__device__ __forceinline__ void wcvt(const float* W, __half* o, int j,
                                     int K, int Nd, int Np) {
    int k = j / Np, n = j - k * Np;
    float v = (k < K && n < Nd) ? W[(size_t)k * Nd + n] : 0.0f;
    o[j] = __float2half_rn(v);
}
#define W1N (64 * 384)
#define W2N (352 * 192)
#define W3N (192 * 96)
#define W4N (96 * 96)
#define WTOT (W1N + W2N + W3N + W4N)
__global__ void k_prep(const float* __restrict__ W1, const float* __restrict__ W2,
                       const float* __restrict__ W3, const float* __restrict__ W4,
                       __half* __restrict__ w1, __half* __restrict__ w2,
                       __half* __restrict__ w3, __half* __restrict__ w4,
                       int* __restrict__ cnt, int* __restrict__ off) {
    int i = blockIdx.x * blockDim.x + threadIdx.x;
    if (i == 0) off[NN] = EE;
    if (i < NN) cnt[i] = 0;
    if (i < W1N) wcvt(W1, w1, i, 35, 336, 384);
    else if (i < W1N + W2N) wcvt(W2, w2, i - W1N, 336, 168, 192);
    else if (i < W1N + W2N + W3N) wcvt(W3, w3, i - W1N - W2N, 168, 84, 96);
    else if (i < WTOT) wcvt(W4, w4, i - W1N - W2N - W3N, 84, 42, 96);
}

// ---------------------------------------------------------------------------
// CSR build
// ---------------------------------------------------------------------------
__global__ void k_count(const int* __restrict__ dst, int* cnt) {
    int e = blockIdx.x * blockDim.x + threadIdx.x;
    if (e < EE) atomicAdd(&cnt[dst[e]], 1);
}
__global__ void k_scan1(const int* __restrict__ cnt, int* __restrict__ off,
                        int* __restrict__ part, float* __restrict__ dinv) {
    __shared__ int s[1024];
    int t = threadIdx.x;
    int i = blockIdx.x * 1024 + t;
    int v = (i < NN) ? cnt[i] : 0;
    if (i < NN) dinv[i] = rsqrtf((float)v + 1.0f);
    s[t] = v;
    __syncthreads();
    for (int d = 1; d < 1024; d <<= 1) {
        int u = (t >= d) ? s[t - d] : 0;
        __syncthreads();
        s[t] += u;
        __syncthreads();
    }
    if (i < NN) off[i] = s[t] - v;          // block-local exclusive
    if (t == 1023) part[blockIdx.x] = s[1023];
}
// scan3: finalize offsets (each block redundantly scans the 98 partials) and
// ALSO does the pad+scale of x -> xx (grid-stride) to save a launch.
__global__ void k_scan3(int* __restrict__ off, const int* __restrict__ part,
                        const float* __restrict__ x, const float* __restrict__ dinv,
                        __half* __restrict__ xx) {
    __shared__ int s[128];
    int t = threadIdx.x;
    if (t < 128) s[t] = (t < NPART) ? part[t] : 0;
    __syncthreads();
    for (int d = 1; d < 128; d <<= 1) {
        int u = 0;
        if (t < 128 && t >= d) u = s[t - d];
        __syncthreads();
        if (t < 128) s[t] += u;
        __syncthreads();
    }
    int base = (blockIdx.x > 0) ? s[blockIdx.x - 1] : 0;   // exclusive prefix
    int i = blockIdx.x * 1024 + t;
    if (i < NN) off[i] += base;
    // fused pad+scale: xx[n,c] = fp16(dinv[n] * pad(x)[n,c])
    for (long j = (long)blockIdx.x * 1024 + t; j < (long)NN * 36; j += (long)NPART * 1024) {
        int n = (int)(j / 36), c = (int)(j - (long)n * 36);
        float v = (c < 35) ? x[(size_t)n * 35 + c] : 0.0f;
        xx[j] = __float2half_rn(v * dinv[n]);
    }
}
// fill reusing cnt via atomic decrement
__global__ void k_fill(const int* __restrict__ src, const int* __restrict__ dst,
                       const int* __restrict__ off, int* cnt, int* __restrict__ adj) {
    int e = blockIdx.x * blockDim.x + threadIdx.x;
    if (e >= EE) return;
    int d = dst[e];
    int p = off[d] + atomicAdd(&cnt[d], -1) - 1;
    adj[p] = src[e];
}

// ---------------------------------------------------------------------------
// CSR gather aggregation on fp16 arrays (fp32 accumulate, 4-way unrolled)
// ---------------------------------------------------------------------------
template <int D, int V, bool RBS>
__global__ void __launch_bounds__(252)
k_agg(const int* __restrict__ off, const int* __restrict__ adj,
      const float* __restrict__ dinv, const __half* __restrict__ tt,
      const float* __restrict__ bias, __half* __restrict__ p) {
    constexpr int G = D / V;
    constexpr int NPB = 252 / G;
    int g = threadIdx.x / G;
    int c = (threadIdx.x - g * G) * V;
    int node = blockIdx.x * NPB + g;
    if (node >= NN) return;
    int ib = off[node], ie = off[node + 1];
    float acc[V], acc2[V];
    float t0[V], t1[V], t2[V], t3[V];
    ldh<V>(tt + (size_t)node * D + c, acc);
#pragma unroll
    for (int v = 0; v < V; v++) acc2[v] = 0.0f;
    int i = ib;
    for (; i + 4 <= ie; i += 4) {
        int s0 = adj[i], s1 = adj[i + 1], s2 = adj[i + 2], s3 = adj[i + 3];
        ldh<V>(tt + (size_t)s0 * D + c, t0);
        ldh<V>(tt + (size_t)s1 * D + c, t1);
        ldh<V>(tt + (size_t)s2 * D + c, t2);
        ldh<V>(tt + (size_t)s3 * D + c, t3);
#pragma unroll
        for (int v = 0; v < V; v++) {
            acc[v]  += t0[v] + t1[v];
            acc2[v] += t2[v] + t3[v];
        }
    }
    for (; i < ie; i++) {
        int s0 = adj[i];
        ldh<V>(tt + (size_t)s0 * D + c, t0);
#pragma unroll
        for (int v = 0; v < V; v++) acc[v] += t0[v];
    }
    float sc = dinv[node];
#pragma unroll
    for (int v = 0; v < V; v++) {
        float f = (acc[v] + acc2[v]) * sc;
        if (RBS) f = fmaxf(f + bias[c + v], 0.0f) * sc;
        acc[v] = f;
    }
    sth<V>(p + (size_t)node * D + c, acc);
}

// ---------------------------------------------------------------------------
// wmma fp16 GEMM, register-staged DOUBLE-BUFFERED chunks.
// Block 128x96, 8 warps (4x2), warp 32x48, k-chunk 32, fp32 accumulate.
// Per chunk: prefetch next chunk into regs during MMA, one sync per chunk.
// ---------------------------------------------------------------------------
template <bool IN_RELU, bool OUT_RELU, bool OUT_SCALE>
__global__ void __launch_bounds__(256)
k_wgemm(const __half* __restrict__ A, int Kphys, const float* __restrict__ binA,
        const __half* __restrict__ B,
        const float* __restrict__ bout, __half* __restrict__ C,
        const float* __restrict__ dinv, int M, int Nd, int Kp, int Np) {
    __shared__ __half Ash[2][128][40];
    __shared__ __half Bsh[2][32][104];
    __shared__ float stage[8][256];

    int tid = threadIdx.x;
    int wid = tid >> 5;
    int lane = tid & 31;
    int wm = wid & 3;
    int wn = wid >> 2;
    int row0 = blockIdx.x * 128;
    int col0 = blockIdx.y * 96;
    bool al8 = ((Nd & 3) == 0);

    wmma::fragment<wmma::accumulator, 16, 16, 16, float> acc[2][3];
#pragma unroll
    for (int mi = 0; mi < 2; mi++)
#pragma unroll
        for (int ni = 0; ni < 3; ni++) wmma::fill_fragment(acc[mi][ni], 0.0f);

    uint2 aReg[4], bReg[3];

    auto load_regs = [&](int ch) {
#pragma unroll
        for (int l = 0; l < 4; l++) {
            int i = tid + l * 256;
            int r = i >> 3, j4 = (i & 7) * 4;
            int grow = row0 + r, gk = ch * 32 + j4;
            uint2 u = make_uint2(0u, 0u);
            if (grow < M && gk < Kphys) {
                u = *(const uint2*)(A + (size_t)grow * Kphys + gk);
                if (IN_RELU) {
                    const __half2* h = (const __half2*)&u;
                    float2 f0 = __half22float2(h[0]);
                    float2 f1 = __half22float2(h[1]);
                    float4 b = *(const float4*)(binA + gk);
                    __half2 o0 = __floats2half2_rn(fmaxf(f0.x + b.x, 0.f), fmaxf(f0.y + b.y, 0.f));
                    __half2 o1 = __floats2half2_rn(fmaxf(f1.x + b.z, 0.f), fmaxf(f1.y + b.w, 0.f));
                    u = make_uint2(*(uint32_t*)&o0, *(uint32_t*)&o1);
                }
            }
            aReg[l] = u;
        }
#pragma unroll
        for (int l = 0; l < 3; l++) {
            int idx = tid + l * 256;
            int k = idx / 24, j4 = (idx - k * 24) * 4;
            size_t src = (size_t)(ch * 32 + k) * Np + col0 + j4;
            bReg[l] = *(const uint2*)(B + src);
        }
    };
    auto store_regs = [&](int buf) {
#pragma unroll
        for (int l = 0; l < 4; l++) {
            int i = tid + l * 256;
            int r = i >> 3, j4 = (i & 7) * 4;
            *(uint2*)&Ash[buf][r][j4] = aReg[l];
        }
#pragma unroll
        for (int l = 0; l < 3; l++) {
            int idx = tid + l * 256;
            int k = idx / 24, j4 = (idx - k * 24) * 4;
            *(uint2*)&Bsh[buf][k][j4] = bReg[l];
        }
    };

    int nch = Kp >> 5;
    load_regs(0);
    store_regs(0);
    __syncthreads();

    for (int ch = 0; ch < nch; ch++) {
        int buf = ch & 1;
        if (ch + 1 < nch) load_regs(ch + 1);
#pragma unroll
        for (int kk = 0; kk < 32; kk += 16) {
            wmma::fragment<wmma::matrix_a, 16, 16, 16, __half, wmma::row_major> af[2];
            wmma::fragment<wmma::matrix_b, 16, 16, 16, __half, wmma::row_major> bf[3];
#pragma unroll
            for (int mi = 0; mi < 2; mi++)
                wmma::load_matrix_sync(af[mi], &Ash[buf][wm * 32 + mi * 16][kk], 40);
#pragma unroll
            for (int ni = 0; ni < 3; ni++)
                wmma::load_matrix_sync(bf[ni], &Bsh[buf][kk][wn * 48 + ni * 16], 104);
#pragma unroll
            for (int mi = 0; mi < 2; mi++)
#pragma unroll
                for (int ni = 0; ni < 3; ni++)
                    wmma::mma_sync(acc[mi][ni], af[mi], bf[ni], acc[mi][ni]);
        }
        if (ch + 1 < nch) store_regs(buf ^ 1);
        __syncthreads();
    }

    // epilogue
#pragma unroll
    for (int mi = 0; mi < 2; mi++) {
#pragma unroll
        for (int ni = 0; ni < 3; ni++) {
            wmma::store_matrix_sync(stage[wid], acc[mi][ni], 16, wmma::mem_row_major);
            __syncwarp();
            int r = lane >> 1, cg = (lane & 1) * 8;
            int grow = row0 + wm * 32 + mi * 16 + r;
            int col = col0 + wn * 48 + ni * 16 + cg;
            if (grow < M) {
                float s = OUT_SCALE ? dinv[grow] : 1.0f;
                const float* st = &stage[wid][r * 16 + cg];
#pragma unroll
                for (int h4 = 0; h4 < 2; h4++) {
                    int cc = col + h4 * 4;
                    if (cc >= Nd) continue;
                    float f[4];
#pragma unroll
                    for (int j = 0; j < 4; j++) {
                        float v = st[h4 * 4 + j];
                        if (OUT_RELU) v = fmaxf(v + bout[cc + j], 0.0f);
                        if (OUT_SCALE) v *= s;
                        f[j] = v;
                    }
                    __half* dst = C + (size_t)grow * Nd + cc;
                    if (al8 && cc + 4 <= Nd) {
                        sth<4>(dst, f);
                    } else {
                        int nw = Nd - cc; if (nw > 4) nw = 4;
                        for (int j = 0; j + 2 <= nw; j += 2) sth<2>(dst + j, f + j);
                    }
                }
            }
            __syncwarp();
        }
    }
}

// ---------------------------------------------------------------------------
// Final fused head: p5 fp16 in, fp32 math, log_softmax out
// ---------------------------------------------------------------------------
__global__ void __launch_bounds__(128)
k_final(const __half* __restrict__ p5,
        const float* __restrict__ Wmu, const float* __restrict__ bmu,
        const float* __restrict__ Wls, const float* __restrict__ bls,
        const float* __restrict__ eps, float* __restrict__ out) {
    __shared__ float sWmu[42 * 21];
    __shared__ float sWls[42 * 21];
    __shared__ float sbmu[21];
    __shared__ float sbls[21];
    for (int i = threadIdx.x; i < 42 * 21; i += blockDim.x) {
        sWmu[i] = Wmu[i];
        sWls[i] = Wls[i];
    }
    if (threadIdx.x < 21) {
        sbmu[threadIdx.x] = bmu[threadIdx.x];
        sbls[threadIdx.x] = bls[threadIdx.x];
    }
    __syncthreads();

    int n = blockIdx.x * blockDim.x + threadIdx.x;
    if (n >= NN) return;

    float xr[42];
#pragma unroll
    for (int i = 0; i < 21; i++) {
        float2 t = __half22float2(*(const __half2*)(p5 + (size_t)n * 42 + 2 * i));
        xr[2 * i] = t.x; xr[2 * i + 1] = t.y;
    }

    float z[21];
#pragma unroll
    for (int j = 0; j < 21; j++) {
        float mu = sbmu[j];
        float ls = sbls[j];
#pragma unroll
        for (int i = 0; i < 42; i++) {
            mu += xr[i] * sWmu[i * 21 + j];
            ls += xr[i] * sWls[i * 21 + j];
        }
        ls = fminf(ls, 10.0f);
        z[j] = mu + eps[(size_t)n * 21 + j] * expf(ls);
    }
    float m = z[0];
#pragma unroll
    for (int j = 1; j < 21; j++) m = fmaxf(m, z[j]);
    float s = 0.0f;
#pragma unroll
    for (int j = 0; j < 21; j++) s += expf(z[j] - m);
    float lse = m + logf(s);
#pragma unroll
    for (int j = 0; j < 21; j++) out[(size_t)n * 21 + j] = z[j] - lse;
}

// ---------------------------------------------------------------------------
static inline int cdiv(long a, long b) { return (int)((a + b - 1) / b); }

extern "C" void kernel_launch(void* const* d_in, const int* in_sizes, int n_in,
                              void* d_out, int out_size) {
    const float* x    = (const float*)d_in[0];
    const int*   ei   = (const int*)  d_in[1];
    const float* eps  = (const float*)d_in[2];
    const float* W1   = (const float*)d_in[3];
    const float* b1   = (const float*)d_in[4];
    const float* W2   = (const float*)d_in[5];
    const float* b2   = (const float*)d_in[6];
    const float* W3   = (const float*)d_in[7];
    const float* b3   = (const float*)d_in[8];
    const float* W4   = (const float*)d_in[9];
    const float* b4   = (const float*)d_in[10];
    const float* Wmu  = (const float*)d_in[11];
    const float* bmu  = (const float*)d_in[12];
    const float* Wls  = (const float*)d_in[13];
    const float* bls  = (const float*)d_in[14];
    float* out = (float*)d_out;

    float* dinv;
    __half *xx, *p0, *a1, *tt2, *p2, *tt3, *p3, *tt4, *a4s, *p5;
    __half *w1, *w2, *w3, *w4;
    int *cnt, *off, *adj, *part;
    cudaGetSymbolAddress((void**)&dinv, g_dinv);
    cudaGetSymbolAddress((void**)&xx,  g_xx);
    cudaGetSymbolAddress((void**)&p0,  g_p0);
    cudaGetSymbolAddress((void**)&a1,  g_a1);
    cudaGetSymbolAddress((void**)&tt2, g_tt2);
    cudaGetSymbolAddress((void**)&p2,  g_p2);
    cudaGetSymbolAddress((void**)&tt3, g_tt3);
    cudaGetSymbolAddress((void**)&p3,  g_p3);
    cudaGetSymbolAddress((void**)&tt4, g_tt4);
    cudaGetSymbolAddress((void**)&a4s, g_a4s);
    cudaGetSymbolAddress((void**)&p5,  g_p5);
    cudaGetSymbolAddress((void**)&w1, g_w1);
    cudaGetSymbolAddress((void**)&w2, g_w2);
    cudaGetSymbolAddress((void**)&w3, g_w3);
    cudaGetSymbolAddress((void**)&w4, g_w4);
    cudaGetSymbolAddress((void**)&cnt, g_cnt);
    cudaGetSymbolAddress((void**)&off, g_off);
    cudaGetSymbolAddress((void**)&adj, g_adj);
    cudaGetSymbolAddress((void**)&part, g_part);

    const int* src = ei;
    const int* dst = ei + EE;

    // ---- fused prep + CSR build (+pad/scale fused into scan3) ----
    long prep_n = (long)NN > (long)WTOT ? (long)NN : (long)WTOT;
    k_prep<<<cdiv(prep_n, 256), 256>>>(W1, W2, W3, W4, w1, w2, w3, w4, cnt, off);
    k_count<<<cdiv(EE, 256), 256>>>(dst, cnt);
    k_scan1<<<NPART, 1024>>>(cnt, off, part, dinv);
    k_scan3<<<NPART, 1024>>>(off, part, x, dinv, xx);
    k_fill<<<cdiv(EE, 256), 256>>>(src, dst, off, cnt, adj);

    int gm = cdiv(NN, 128);

    // ---- conv1: aggregate x (D=36), wmma GEMM 35->336 (+b1, relu) ----
    k_agg<36, 4, false><<<cdiv(NN, 28), 252>>>(off, adj, dinv, xx, nullptr, p0);
    k_wgemm<false, true, false><<<dim3(gm, 4), 256>>>(
        p0, 36, nullptr, w1, b1, a1, nullptr, NN, 336, 64, 384);

    // ---- conv2: wmma GEMM 336->168 (scaled out), aggregate ----
    k_wgemm<false, false, true><<<dim3(gm, 2), 256>>>(
        a1, 336, nullptr, w2, nullptr, tt2, dinv, NN, 168, 352, 192);
    k_agg<168, 8, false><<<cdiv(NN, 12), 252>>>(off, adj, dinv, tt2, nullptr, p2);

    // ---- conv3: in = relu(p2+b2), wmma GEMM 168->84, scaled out ----
    k_wgemm<true, false, true><<<dim3(gm, 1), 256>>>(
        p2, 168, b2, w3, nullptr, tt3, dinv, NN, 84, 192, 96);
    k_agg<84, 4, false><<<cdiv(NN, 12), 252>>>(off, adj, dinv, tt3, nullptr, p3);

    // ---- conv4: in = relu(p3+b3), wmma GEMM 84->42, scaled out ----
    k_wgemm<true, false, true><<<dim3(gm, 1), 256>>>(
        p3, 84, b3, w4, nullptr, tt4, dinv, NN, 42, 96, 96);
    k_agg<42, 2, true><<<cdiv(NN, 12), 252>>>(off, adj, dinv, tt4, b4, a4s);

    // ---- shared head propagation ----
    k_agg<42, 2, false><<<cdiv(NN, 12), 252>>>(off, adj, dinv, a4s, nullptr, p5);

    // ---- fused heads + reparam + log_softmax ----
    k_final<<<cdiv(NN, 128), 128>>>(p5, Wmu, bmu, Wls, bls, eps, out);
}